// round 12
// baseline (speedup 1.0000x reference)
#include <cuda_runtime.h>
#include <cuda_bf16.h>
#include <math.h>

#define NN    4096
#define FEATD 512
#define DD    64
#define KCLU  100
#define SPAD  128
#define TOK   101
#define LNUM  3
#define KSPLIT 16
#define KC    (NN / KSPLIT)     // 256
#define NIT   (KC / 16)         // 16

// ---------------- device scratch (no allocation allowed) ----------------
__device__ float g_xc[NN*DD];
__device__ float g_y [NN*DD];
__device__ float g_yn[NN*DD];
__device__ float g_dg[NN];
__device__ float g_bnsum[DD];
__device__ float g_bnsq [DD];
__device__ float g_s[NN*SPAD];
__device__ float g_num;
__device__ float g_den;
__device__ float g_pool[KCLU*DD];
__device__ float g_ssm [KCLU*KCLU];
__device__ float g_t  [TOK*DD];
__device__ float g_qkvb[2][TOK*192];
__device__ __nv_bfloat16 g_xcT_h[DD*NN];   // xc^T hi  [64][4096]
__device__ __nv_bfloat16 g_xcT_l[DD*NN];   // xc^T lo
__device__ __nv_bfloat16 g_sT_h [SPAD*NN]; // s^T hi  [128][4096] (rows >=100 zero)

// ---------------- bf16 MMA helper (m16n8k16, fp32 accum) ----------------
__device__ __forceinline__ void mma16816(float* d, const unsigned* a, const unsigned* b)
{
    asm volatile(
        "mma.sync.aligned.m16n8k16.row.col.f32.bf16.bf16.f32 "
        "{%0,%1,%2,%3},{%4,%5,%6,%7},{%8,%9},{%0,%1,%2,%3};"
        : "+f"(d[0]), "+f"(d[1]), "+f"(d[2]), "+f"(d[3])
        : "r"(a[0]), "r"(a[1]), "r"(a[2]), "r"(a[3]), "r"(b[0]), "r"(b[1]));
}

// ---------------- K1: xc = node_feat @ conv_w  (4096x512x64) ----------------
__global__ __launch_bounds__(256) void k_gemm_xc(const float* __restrict__ X,
                                                 const float* __restrict__ W)
{
    const int m0 = blockIdx.x * 64;
    __shared__ float As[16][68];
    __shared__ float Bs[16][64];
    const int tid = threadIdx.x;
    const int tx = tid & 15, ty = tid >> 4;
    const int ar = tid >> 2, ac = (tid & 3) << 2;
    const int br = tid >> 4, bc = (tid & 15) << 2;
    float acc[4][4] = {};
    const float* Ap = X + (m0 + ar) * FEATD;
    float4 aP = *(const float4*)(Ap + ac);
    float4 bP = *(const float4*)(W + br * 64 + bc);
    for (int k0 = 0; k0 < FEATD; k0 += 16) {
        As[ac+0][ar]=aP.x; As[ac+1][ar]=aP.y; As[ac+2][ar]=aP.z; As[ac+3][ar]=aP.w;
        *(float4*)&Bs[br][bc] = bP;
        __syncthreads();
        int kn = k0 + 16;
        if (kn < FEATD) {
            aP = *(const float4*)(Ap + kn + ac);
            bP = *(const float4*)(W + (kn + br) * 64 + bc);
        }
        #pragma unroll
        for (int kk = 0; kk < 16; kk++) {
            float4 a = *(const float4*)&As[kk][ty<<2];
            float4 b = *(const float4*)&Bs[kk][tx<<2];
            float av[4]={a.x,a.y,a.z,a.w}, bv[4]={b.x,b.y,b.z,b.w};
            #pragma unroll
            for (int i=0;i<4;i++)
                #pragma unroll
                for (int j=0;j<4;j++) acc[i][j] += av[i]*bv[j];
        }
        __syncthreads();
    }
    #pragma unroll
    for (int i=0;i<4;i++)
        #pragma unroll
        for (int j=0;j<4;j++)
            g_xc[(m0 + (ty<<2) + i)*DD + (tx<<2) + j] = acc[i][j];
}

// ---------------- K0: init y = xc + conv_b, zero accumulators ----------------
__global__ void k_init(const float* __restrict__ conv_b)
{
    int idx = blockIdx.x*blockDim.x + threadIdx.x;
    if (idx < NN*DD) g_y[idx] = g_xc[idx] + conv_b[idx & 63];
    if (idx < NN) g_dg[idx] = 0.f;
    if (idx < DD) { g_bnsum[idx]=0.f; g_bnsq[idx]=0.f; }
    if (idx < KCLU*DD) g_pool[idx]=0.f;
    if (idx < KCLU*KCLU) g_ssm[idx]=0.f;
    if (idx == 0) { g_num=0.f; g_den=0.f; }
}

// ---------------- K1b: transpose + split xc -> bf16 hi/lo [64][4096] ----------------
__global__ __launch_bounds__(256) void k_xcT()
{
    __shared__ float T[64][65];
    const int m0 = blockIdx.x * 64;
    const int tid = threadIdx.x;
    for (int i = tid; i < 64*64; i += 256) {
        int r = i >> 6, c = i & 63;
        T[r][c] = g_xc[(m0 + r)*DD + c];
    }
    __syncthreads();
    for (int i = tid; i < 64*64; i += 256) {
        int n = i >> 6, m = i & 63;
        float v = T[m][n];
        __nv_bfloat16 h = __float2bfloat16_rn(v);
        g_xcT_h[(size_t)n*NN + m0 + m] = h;
        g_xcT_l[(size_t)n*NN + m0 + m] = __float2bfloat16_rn(v - __bfloat162float(h));
    }
}

// ---------------- PASS1: y += adj @ xc (tensor, 3-product) + degrees -- r3 proven ----
__global__ __launch_bounds__(256) void k_pass1(const float* __restrict__ adj)
{
    const int m0  = blockIdx.x * 64;
    const int kc0 = blockIdx.y * KC;
    __shared__ __nv_bfloat16 Ah[64][24], Al[64][24], Bh[64][24], Bl[64][24];
    const int tid = threadIdx.x;
    const int lane = tid & 31, wid = tid >> 5;
    const int warpM = wid & 1, warpN = wid >> 1;
    const int fr = lane >> 2, kp = (lane & 3) << 1;
    const int ar = tid >> 2, ac4 = tid & 3;
    const int bn = (tid & 127) >> 1, bhalf = tid & 1;

    const float* ap = adj + (size_t)(m0 + ar) * NN + kc0 + ac4 * 4;
    const __nv_bfloat16* bp = (tid < 128 ? g_xcT_h : g_xcT_l) + (size_t)bn * NN + kc0 + bhalf * 8;

    float D[2][2][4] = {};
    float dsum = 0.f;
    float4 pa = *(const float4*)ap;
    uint4  pb = *(const uint4*)bp;

    for (int it = 0; it < NIT; it++) {
        float v[4] = {pa.x, pa.y, pa.z, pa.w};
        union { __nv_bfloat16 h[4]; uint2 u; } uh, ul;
        #pragma unroll
        for (int j = 0; j < 4; j++) {
            __nv_bfloat16 hh = __float2bfloat16_rn(v[j]);
            uh.h[j] = hh;
            ul.h[j] = __float2bfloat16_rn(v[j] - __bfloat162float(hh));
            dsum += v[j];
        }
        *(uint2*)&Ah[ar][ac4*4] = uh.u;
        *(uint2*)&Al[ar][ac4*4] = ul.u;
        if (tid < 128) *(uint4*)&Bh[bn][bhalf*8] = pb;
        else           *(uint4*)&Bl[bn][bhalf*8] = pb;
        __syncthreads();
        if (it + 1 < NIT) {
            ap += 16; bp += 16;
            pa = *(const float4*)ap;
            pb = *(const uint4*)bp;
        }
        unsigned a_h[2][4], a_l[2][4];
        #pragma unroll
        for (int mi = 0; mi < 2; mi++) {
            int row = warpM*32 + mi*16 + fr;
            a_h[mi][0] = *(const unsigned*)&Ah[row][kp];
            a_h[mi][1] = *(const unsigned*)&Ah[row+8][kp];
            a_h[mi][2] = *(const unsigned*)&Ah[row][kp+8];
            a_h[mi][3] = *(const unsigned*)&Ah[row+8][kp+8];
            a_l[mi][0] = *(const unsigned*)&Al[row][kp];
            a_l[mi][1] = *(const unsigned*)&Al[row+8][kp];
            a_l[mi][2] = *(const unsigned*)&Al[row][kp+8];
            a_l[mi][3] = *(const unsigned*)&Al[row+8][kp+8];
        }
        unsigned b_h[2][2], b_l[2][2];
        #pragma unroll
        for (int nj = 0; nj < 2; nj++) {
            int n = warpN*16 + nj*8 + fr;
            b_h[nj][0] = *(const unsigned*)&Bh[n][kp];
            b_h[nj][1] = *(const unsigned*)&Bh[n][kp+8];
            b_l[nj][0] = *(const unsigned*)&Bl[n][kp];
            b_l[nj][1] = *(const unsigned*)&Bl[n][kp+8];
        }
        #pragma unroll
        for (int mi = 0; mi < 2; mi++)
            #pragma unroll
            for (int nj = 0; nj < 2; nj++) {
                mma16816(D[mi][nj], a_h[mi], b_h[nj]);
                mma16816(D[mi][nj], a_h[mi], b_l[nj]);
                mma16816(D[mi][nj], a_l[mi], b_h[nj]);
            }
        __syncthreads();
    }
    atomicAdd(&g_dg[m0 + ar], dsum);
    #pragma unroll
    for (int mi = 0; mi < 2; mi++)
        #pragma unroll
        for (int nj = 0; nj < 2; nj++) {
            int m = m0 + warpM*32 + mi*16 + (lane >> 2);
            int n = warpN*16 + nj*8 + ((lane & 3) << 1);
            atomicAdd(&g_y[m*DD + n],       D[mi][nj][0]);
            atomicAdd(&g_y[m*DD + n + 1],   D[mi][nj][1]);
            atomicAdd(&g_y[(m+8)*DD + n],   D[mi][nj][2]);
            atomicAdd(&g_y[(m+8)*DD + n+1], D[mi][nj][3]);
        }
}

// ---------------- K3a: BN statistics over 4096 rows ----------------
__global__ void k_bnstats()
{
    __shared__ float sh [256];
    __shared__ float sh2[256];
    int tid = threadIdx.x;
    int ch = tid & 63;
    int base = blockIdx.x * 64;
    float s = 0.f, q = 0.f;
    for (int r = base + (tid >> 6); r < base + 64; r += 4) {
        float v = g_y[r*DD + ch];
        s += v; q += v*v;
    }
    sh[tid] = s; sh2[tid] = q;
    __syncthreads();
    if (tid < 64) {
        s = sh[tid] + sh[tid+64] + sh[tid+128] + sh[tid+192];
        q = sh2[tid] + sh2[tid+64] + sh2[tid+128] + sh2[tid+192];
        atomicAdd(&g_bnsum[tid], s);
        atomicAdd(&g_bnsq[tid], q);
    }
}

// ---------------- K3b: warp-per-row BN + L2norm + pool softmax + den + s^T ----------------
// grid 512 (one row per warp, 8 rows/block); pool_w staged in smem.
__global__ __launch_bounds__(256) void k_rowops(const float* __restrict__ bn_g,
                                                const float* __restrict__ bn_b,
                                                const float* __restrict__ pool_w,
                                                const float* __restrict__ pool_b)
{
    __shared__ float pw[6432];
    const int tid = threadIdx.x;
    const int lane = tid & 31, wid = tid >> 5;
    for (int i = tid; i < 6400; i += 256) pw[i] = pool_w[i];
    float mean0 = g_bnsum[lane]      * (1.0f/NN);
    float mean1 = g_bnsum[lane+32]   * (1.0f/NN);
    float rs0 = rsqrtf(g_bnsq[lane]    * (1.0f/NN) - mean0*mean0 + 1e-5f) * bn_g[lane];
    float rs1 = rsqrtf(g_bnsq[lane+32] * (1.0f/NN) - mean1*mean1 + 1e-5f) * bn_g[lane+32];
    float bb0 = bn_b[lane], bb1 = bn_b[lane+32];
    float pb[4];
    #pragma unroll
    for (int b = 0; b < 4; b++) {
        int c = lane + 32*b;
        pb[b] = (c < KCLU) ? pool_b[c] : 0.f;
    }
    __syncthreads();
    const int row = blockIdx.x*8 + wid;
    float v0 = (g_y[row*DD + lane]      - mean0) * rs0 + bb0;
    float v1 = (g_y[row*DD + lane + 32] - mean1) * rs1 + bb1;
    float sq = v0*v0 + v1*v1;
    #pragma unroll
    for (int off = 16; off; off >>= 1) sq += __shfl_xor_sync(0xffffffffu, sq, off);
    float inv = 1.0f / fmaxf(sqrtf(sq), 1e-12f);
    float yn0 = v0 * inv, yn1 = v1 * inv;
    g_yn[row*DD + lane]      = yn0;
    g_yn[row*DD + lane + 32] = yn1;
    float lg[4] = {0.f, 0.f, 0.f, 0.f};
    #pragma unroll 8
    for (int d = 0; d < 64; d++) {
        float yd = __shfl_sync(0xffffffffu, (d < 32) ? yn0 : yn1, d & 31);
        const float* pr = pw + d*100 + lane;
        lg[0] += yd * pr[0];
        lg[1] += yd * pr[32];
        lg[2] += yd * pr[64];
        lg[3] += yd * pr[96];   // valid only for lane<4 (c<100); else discarded
    }
    #pragma unroll
    for (int b = 0; b < 4; b++) lg[b] += pb[b];
    float mx = fmaxf(fmaxf(lg[0], lg[1]), lg[2]);
    if (lane < 4) mx = fmaxf(mx, lg[3]);
    #pragma unroll
    for (int off = 16; off; off >>= 1) mx = fmaxf(mx, __shfl_xor_sync(0xffffffffu, mx, off));
    float e0 = expf(lg[0]-mx), e1 = expf(lg[1]-mx), e2 = expf(lg[2]-mx);
    float e3 = (lane < 4) ? expf(lg[3]-mx) : 0.f;
    float sum = e0+e1+e2+e3;
    #pragma unroll
    for (int off = 16; off; off >>= 1) sum += __shfl_xor_sync(0xffffffffu, sum, off);
    float is = 1.0f / sum;
    float p0 = e0*is, p1 = e1*is, p2 = e2*is, p3 = e3*is;
    g_s[row*SPAD + lane]      = p0;
    g_s[row*SPAD + lane + 32] = p1;
    g_s[row*SPAD + lane + 64] = p2;
    g_s[row*SPAD + lane + 96] = p3;
    g_sT_h[(size_t)(lane)     *NN + row] = __float2bfloat16_rn(p0);
    g_sT_h[(size_t)(lane + 32)*NN + row] = __float2bfloat16_rn(p1);
    g_sT_h[(size_t)(lane + 64)*NN + row] = __float2bfloat16_rn(p2);
    g_sT_h[(size_t)(lane + 96)*NN + row] = __float2bfloat16_rn(p3);
    float s2 = p0*p0 + p1*p1 + p2*p2 + p3*p3;
    #pragma unroll
    for (int off = 16; off; off >>= 1) s2 += __shfl_xor_sync(0xffffffffu, s2, off);
    if (lane == 0) atomicAdd(&g_den, g_dg[row] * s2);
}

// ---------------- PASS2: num = <s, adj @ s> (tensor, single bf16) -- r3 proven ----------------
__global__ __launch_bounds__(256) void k_pass2(const float* __restrict__ adj)
{
    const int m0  = blockIdx.x * 64;
    const int kc0 = blockIdx.y * KC;
    __shared__ __nv_bfloat16 Ah[64][24], Sh[128][24];
    __shared__ float red[256];
    const int tid = threadIdx.x;
    const int lane = tid & 31, wid = tid >> 5;
    const int warpM = wid & 1, warpN = wid >> 1;
    const int fr = lane >> 2, kp = (lane & 3) << 1;
    const int ar = tid >> 2, ac4 = tid & 3;
    const int sn = tid >> 1, shalf = tid & 1;

    const float* ap = adj + (size_t)(m0 + ar) * NN + kc0 + ac4 * 4;
    const __nv_bfloat16* sp = g_sT_h + (size_t)sn * NN + kc0 + shalf * 8;

    float D[2][4][4] = {};
    float4 pa = *(const float4*)ap;
    uint4  ps = *(const uint4*)sp;

    for (int it = 0; it < NIT; it++) {
        float v[4] = {pa.x, pa.y, pa.z, pa.w};
        union { __nv_bfloat16 h[4]; uint2 u; } uh;
        #pragma unroll
        for (int j = 0; j < 4; j++) uh.h[j] = __float2bfloat16_rn(v[j]);
        *(uint2*)&Ah[ar][ac4*4] = uh.u;
        *(uint4*)&Sh[sn][shalf*8] = ps;
        __syncthreads();
        if (it + 1 < NIT) {
            ap += 16; sp += 16;
            pa = *(const float4*)ap;
            ps = *(const uint4*)sp;
        }
        unsigned a_h[2][4];
        #pragma unroll
        for (int mi = 0; mi < 2; mi++) {
            int row = warpM*32 + mi*16 + fr;
            a_h[mi][0] = *(const unsigned*)&Ah[row][kp];
            a_h[mi][1] = *(const unsigned*)&Ah[row+8][kp];
            a_h[mi][2] = *(const unsigned*)&Ah[row][kp+8];
            a_h[mi][3] = *(const unsigned*)&Ah[row+8][kp+8];
        }
        unsigned b_s[4][2];
        #pragma unroll
        for (int nj = 0; nj < 4; nj++) {
            int n = warpN*32 + nj*8 + fr;
            b_s[nj][0] = *(const unsigned*)&Sh[n][kp];
            b_s[nj][1] = *(const unsigned*)&Sh[n][kp+8];
        }
        #pragma unroll
        for (int mi = 0; mi < 2; mi++)
            #pragma unroll
            for (int nj = 0; nj < 4; nj++)
                mma16816(D[mi][nj], a_h[mi], b_s[nj]);
        __syncthreads();
    }
    float part = 0.f;
    #pragma unroll
    for (int mi = 0; mi < 2; mi++)
        #pragma unroll
        for (int nj = 0; nj < 4; nj++) {
            int m = m0 + warpM*32 + mi*16 + (lane >> 2);
            int n = warpN*32 + nj*8 + ((lane & 3) << 1);
            part += D[mi][nj][0]*g_s[m*SPAD + n]     + D[mi][nj][1]*g_s[m*SPAD + n + 1]
                  + D[mi][nj][2]*g_s[(m+8)*SPAD + n] + D[mi][nj][3]*g_s[(m+8)*SPAD + n + 1];
        }
    red[tid] = part;
    __syncthreads();
    for (int s2 = 128; s2 > 0; s2 >>= 1) { if (tid < s2) red[tid] += red[tid+s2]; __syncthreads(); }
    if (tid == 0) atomicAdd(&g_num, red[0]);
}

// ---------------- K5: pool_out = s^T yn, ss = s^T s (64-row chunks) ----------------
__global__ __launch_bounds__(256) void k_pool_ss()
{
    const int k0 = blockIdx.x * 64;
    __shared__ float Ss[64][SPAD];
    __shared__ float Ys[64][64];
    const int tid = threadIdx.x;
    for (int i = tid; i < 64*32; i += 256) {
        int kr = i >> 5, c = (i & 31) << 2;
        *(float4*)&Ss[kr][c] = *(const float4*)(g_s + (size_t)(k0+kr)*SPAD + c);
    }
    for (int i = tid; i < 64*16; i += 256) {
        int kr = i >> 4, c = (i & 15) << 2;
        *(float4*)&Ys[kr][c] = *(const float4*)(g_yn + (size_t)(k0+kr)*64 + c);
    }
    __syncthreads();
    for (int g = tid; g < KCLU*41; g += 256) {
        int m = g / 41;
        int j = (g % 41) * 4;
        const float* cp; int st; float* dst;
        if (j < 64) { cp = &Ys[0][j]; st = 64;   dst = &g_pool[m*DD + j]; }
        else        { cp = &Ss[0][j-64]; st = SPAD; dst = &g_ssm[m*KCLU + (j-64)]; }
        float a0=0.f,a1=0.f,a2=0.f,a3=0.f;
        #pragma unroll 8
        for (int kk = 0; kk < 64; kk++) {
            float sm = Ss[kk][m];
            float4 c = *(const float4*)(cp + kk*st);
            a0 += sm*c.x; a1 += sm*c.y; a2 += sm*c.z; a3 += sm*c.w;
        }
        atomicAdd(dst+0, a0); atomicAdd(dst+1, a1);
        atomicAdd(dst+2, a2); atomicAdd(dst+3, a3);
    }
}

// ---------------- K6: build token + LN1(l=0) + QKV(l=0); block 0 writes losses ----
__global__ __launch_bounds__(256) void k_tok0(const float* __restrict__ cls,
                                              const float* __restrict__ ln_g,
                                              const float* __restrict__ ln_b,
                                              const float* __restrict__ w,
                                              const float* __restrict__ b,
                                              float* __restrict__ out)
{
    const int row = blockIdx.x;
    const int tid = threadIdx.x;
    __shared__ float hs[64];
    __shared__ float red[64];
    __shared__ float r1[256], r2[256];
    float v = 0.f;
    if (tid < 64) {
        v = (row == 0) ? cls[tid] : g_pool[(row-1)*DD + tid];
        g_t[row*DD + tid] = v;
        red[tid] = v;
    }
    __syncthreads();
    for (int s2 = 32; s2 > 0; s2 >>= 1) { if (tid < s2) red[tid] += red[tid+s2]; __syncthreads(); }
    float mean = red[0] * (1.0f/64);
    __syncthreads();
    if (tid < 64) { float d = v - mean; red[tid] = d*d; }
    __syncthreads();
    for (int s2 = 32; s2 > 0; s2 >>= 1) { if (tid < s2) red[tid] += red[tid+s2]; __syncthreads(); }
    float var = red[0] * (1.0f/64);
    __syncthreads();
    if (tid < 64)
        hs[tid] = (v - mean) * rsqrtf(var + 1e-6f) * ln_g[tid] + ln_b[tid];
    __syncthreads();
    if (tid < 192) {
        float a = b[tid];
        const float* wp = w + tid;
        #pragma unroll 8
        for (int d = 0; d < 64; d++) a += hs[d] * wp[d*192];
        g_qkvb[0][row*192 + tid] = a;
    }
    if (row == 0) {
        float sq = 0.f, tr = 0.f;
        for (int i = tid; i < KCLU*KCLU; i += 256) {
            float x = g_ssm[i];
            sq += x*x;
            if (i % (KCLU+1) == 0) tr += x;
        }
        r1[tid] = sq; r2[tid] = tr;
        __syncthreads();
        for (int s2 = 128; s2 > 0; s2 >>= 1) { if (tid < s2) { r1[tid]+=r1[tid+s2]; r2[tid]+=r2[tid+s2]; } __syncthreads(); }
        if (tid == 0) {
            float f = sqrtf(r1[0]);
            out[2] = -(g_num / g_den);
            out[3] = sqrtf(fmaxf(2.0f - r2[0] / (5.0f * f), 0.0f));
        }
    }
}

// ---------------- K7: attn + proj + LN2 + FC1 + GELU + FC2, then next LN1+QKV or head ----
__global__ __launch_bounds__(256) void k_fused(const float* __restrict__ proj_w,
                                               const float* __restrict__ proj_b,
                                               const float* __restrict__ ln2_g,
                                               const float* __restrict__ ln2_b,
                                               const float* __restrict__ fc1_w,
                                               const float* __restrict__ fc1_b,
                                               const float* __restrict__ fc2_w,
                                               const float* __restrict__ fc2_b,
                                               const float* __restrict__ ln1_g,
                                               const float* __restrict__ ln1_b,
                                               const float* __restrict__ qkv_w,
                                               const float* __restrict__ qkv_b,
                                               const float* __restrict__ norm_g,
                                               const float* __restrict__ norm_b,
                                               const float* __restrict__ head_w,
                                               const float* __restrict__ head_b,
                                               float* __restrict__ out,
                                               int l, int final_flag)
{
    const int row = blockIdx.x;
    const int tid = threadIdx.x;
    const int lane = tid & 31, wid = tid >> 5;
    const float* qin = g_qkvb[l & 1];
    float*       qout = g_qkvb[(l + 1) & 1];
    __shared__ float osm[64];
    __shared__ float hs[64];
    __shared__ float red[64];
    __shared__ float h1s[256];

    {
        const int h8 = wid * 8;
        float qv[8];
        #pragma unroll
        for (int d = 0; d < 8; d++) qv[d] = qin[row*192 + h8 + d];
        float sc[4];
        #pragma unroll
        for (int i = 0; i < 4; i++) {
            int j = lane + 32*i;
            float s = -3.0e38f;
            if (j < TOK) {
                const float* kp = qin + j*192 + 64 + h8;
                s = 0.f;
                #pragma unroll
                for (int d = 0; d < 8; d++) s += qv[d]*kp[d];
                s *= 0.35355339059327373f;
            }
            sc[i] = s;
        }
        float mx = fmaxf(fmaxf(sc[0],sc[1]), fmaxf(sc[2],sc[3]));
        #pragma unroll
        for (int off=16; off; off>>=1) mx = fmaxf(mx, __shfl_xor_sync(0xffffffffu, mx, off));
        float es[4]; float sum = 0.f;
        #pragma unroll
        for (int i = 0; i < 4; i++) {
            int j = lane + 32*i;
            es[i] = (j < TOK) ? expf(sc[i] - mx) : 0.f;
            sum += es[i];
        }
        #pragma unroll
        for (int off=16; off; off>>=1) sum += __shfl_xor_sync(0xffffffffu, sum, off);
        float inv = 1.0f / sum;
        float acc[8] = {};
        #pragma unroll
        for (int i = 0; i < 4; i++) {
            int j = lane + 32*i;
            if (j < TOK) {
                float p = es[i] * inv;
                const float* vp = qin + j*192 + 128 + h8;
                #pragma unroll
                for (int d = 0; d < 8; d++) acc[d] += p * vp[d];
            }
        }
        #pragma unroll
        for (int d = 0; d < 8; d++) {
            #pragma unroll
            for (int off=16; off; off>>=1) acc[d] += __shfl_xor_sync(0xffffffffu, acc[d], off);
        }
        if (lane == 0) {
            #pragma unroll
            for (int d = 0; d < 8; d++) osm[h8 + d] = acc[d];
        }
    }
    __syncthreads();

    float tnew = 0.f;
    if (tid < 64) {
        float a = proj_b[l*64 + tid];
        const float* wp = proj_w + (size_t)l*64*64 + tid;
        #pragma unroll 8
        for (int k = 0; k < 64; k++) a += osm[k] * wp[k*64];
        tnew = g_t[row*DD + tid] + a;
        red[tid] = tnew;
    }
    __syncthreads();
    for (int s2 = 32; s2 > 0; s2 >>= 1) { if (tid < s2) red[tid] += red[tid+s2]; __syncthreads(); }
    float mean = red[0] * (1.0f/64);
    __syncthreads();
    if (tid < 64) { float d = tnew - mean; red[tid] = d*d; }
    __syncthreads();
    for (int s2 = 32; s2 > 0; s2 >>= 1) { if (tid < s2) red[tid] += red[tid+s2]; __syncthreads(); }
    float var = red[0] * (1.0f/64);
    __syncthreads();
    if (tid < 64)
        hs[tid] = (tnew - mean) * rsqrtf(var + 1e-6f) * ln2_g[l*64 + tid] + ln2_b[l*64 + tid];
    __syncthreads();

    {
        float a = fc1_b[l*256 + tid];
        const float* wp = fc1_w + (size_t)l*64*256 + tid;
        #pragma unroll 8
        for (int d = 0; d < 64; d++) a += hs[d] * wp[d*256];
        h1s[tid] = 0.5f * a * (1.0f + erff(a * 0.7071067811865475f));
    }
    __syncthreads();

    float tfin = 0.f;
    if (tid < 64) {
        float a = fc2_b[l*64 + tid];
        const float* wp = fc2_w + (size_t)l*256*64 + tid;
        #pragma unroll 8
        for (int k = 0; k < 256; k++) a += h1s[k] * wp[k*64];
        tfin = tnew + a;
        red[tid] = tfin;
    }
    __syncthreads();
    for (int s2 = 32; s2 > 0; s2 >>= 1) { if (tid < s2) red[tid] += red[tid+s2]; __syncthreads(); }
    float mean2 = red[0] * (1.0f/64);
    __syncthreads();
    if (tid < 64) { float d = tfin - mean2; red[tid] = d*d; }
    __syncthreads();
    for (int s2 = 32; s2 > 0; s2 >>= 1) { if (tid < s2) red[tid] += red[tid+s2]; __syncthreads(); }
    float var2 = red[0] * (1.0f/64);
    __syncthreads();

    if (!final_flag) {
        if (tid < 64) {
            g_t[row*DD + tid] = tfin;
            hs[tid] = (tfin - mean2) * rsqrtf(var2 + 1e-6f) * ln1_g[(l+1)*64 + tid] + ln1_b[(l+1)*64 + tid];
        }
        __syncthreads();
        if (tid < 192) {
            float a = qkv_b[(l+1)*192 + tid];
            const float* wp = qkv_w + (size_t)(l+1)*64*192 + tid;
            #pragma unroll 8
            for (int d = 0; d < 64; d++) a += hs[d] * wp[d*192];
            qout[row*192 + tid] = a;
        }
    } else {
        float h = 0.f;
        if (tid < 64)
            h = (tfin - mean2) * rsqrtf(var2 + 1e-6f) * norm_g[tid] + norm_b[tid];
        #pragma unroll
        for (int c = 0; c < 2; c++) {
            if (tid < 64) red[tid] = h * head_w[tid*2 + c];
            __syncthreads();
            for (int s2 = 32; s2 > 0; s2 >>= 1) { if (tid < s2) red[tid] += red[tid+s2]; __syncthreads(); }
            if (tid == 0) out[c] = red[0] + head_b[c];
            __syncthreads();
        }
    }
}

// ---------------- launcher ----------------
extern "C" void kernel_launch(void* const* d_in, const int* in_sizes, int n_in,
                              void* d_out, int out_size)
{
    const float* node   = (const float*)d_in[0];
    const float* adj    = (const float*)d_in[1];
    const float* conv_w = (const float*)d_in[2];
    const float* conv_b = (const float*)d_in[3];
    const float* bn_g   = (const float*)d_in[4];
    const float* bn_b   = (const float*)d_in[5];
    const float* pool_w = (const float*)d_in[6];
    const float* pool_b = (const float*)d_in[7];
    const float* cls    = (const float*)d_in[8];
    const float* ln1_g  = (const float*)d_in[9];
    const float* ln1_b  = (const float*)d_in[10];
    const float* qkv_w  = (const float*)d_in[11];
    const float* qkv_b  = (const float*)d_in[12];
    const float* proj_w = (const float*)d_in[13];
    const float* proj_b = (const float*)d_in[14];
    const float* ln2_g  = (const float*)d_in[15];
    const float* ln2_b  = (const float*)d_in[16];
    const float* fc1_w  = (const float*)d_in[17];
    const float* fc1_b  = (const float*)d_in[18];
    const float* fc2_w  = (const float*)d_in[19];
    const float* fc2_b  = (const float*)d_in[20];
    const float* norm_g = (const float*)d_in[21];
    const float* norm_b = (const float*)d_in[22];
    const float* head_w = (const float*)d_in[23];
    const float* head_b = (const float*)d_in[24];
    float* out = (float*)d_out;

    k_gemm_xc<<<NN/64, 256>>>(node, conv_w);
    k_init<<<(NN*DD)/256, 256>>>(conv_b);
    k_xcT<<<NN/64, 256>>>();
    k_pass1<<<dim3(NN/64, KSPLIT), 256>>>(adj);
    k_bnstats<<<NN/64, 256>>>();
    k_rowops<<<NN/8, 256>>>(bn_g, bn_b, pool_w, pool_b);
    k_pass2<<<dim3(NN/64, KSPLIT), 256>>>(adj);
    k_pool_ss<<<NN/64, 256>>>();
    k_tok0<<<TOK, 256>>>(cls, ln1_g, ln1_b, qkv_w, qkv_b, out);
    k_fused<<<TOK, 256>>>(proj_w, proj_b, ln2_g, ln2_b, fc1_w, fc1_b, fc2_w, fc2_b,
                          ln1_g, ln1_b, qkv_w, qkv_b, norm_g, norm_b, head_w, head_b,
                          out, 0, 0);
    k_fused<<<TOK, 256>>>(proj_w, proj_b, ln2_g, ln2_b, fc1_w, fc1_b, fc2_w, fc2_b,
                          ln1_g, ln1_b, qkv_w, qkv_b, norm_g, norm_b, head_w, head_b,
                          out, 1, 0);
    k_fused<<<1, 256>>>(proj_w, proj_b, ln2_g, ln2_b, fc1_w, fc1_b, fc2_w, fc2_b,
                        ln1_g, ln1_b, qkv_w, qkv_b, norm_g, norm_b, head_w, head_b,
                        out, 2, 1);
}

// round 13
// speedup vs baseline: 1.4744x; 1.4744x over previous
#include <cuda_runtime.h>
#include <cuda_bf16.h>
#include <math.h>

#define NN    4096
#define FEATD 512
#define DD    64
#define KCLU  100
#define SPAD  128
#define TOK   101
#define LNUM  3
#define KSPLIT 16
#define KC    (NN / KSPLIT)     // 256
#define NIT   (KC / 16)         // 16

// ---------------- device scratch (no allocation allowed) ----------------
__device__ float g_xc[NN*DD];
__device__ float g_y [NN*DD];
__device__ float g_yn[NN*DD];
__device__ float g_dg[NN];
__device__ float g_bnsum[DD];
__device__ float g_bnsq [DD];
__device__ float g_s[NN*SPAD];
__device__ float g_num;
__device__ float g_den;
__device__ float g_pool[KCLU*DD];
__device__ float g_ssm [KCLU*KCLU];
__device__ float g_t  [TOK*DD];
__device__ float g_qkvb[2][TOK*192];
__device__ __nv_bfloat16 g_xcT_h[DD*NN];   // xc^T hi  [64][4096]
__device__ __nv_bfloat16 g_xcT_l[DD*NN];   // xc^T lo
__device__ __nv_bfloat16 g_sT_h [SPAD*NN]; // s^T hi  [128][4096] (rows >=100 zero)

// ---------------- bf16 MMA helper (m16n8k16, fp32 accum) ----------------
__device__ __forceinline__ void mma16816(float* d, const unsigned* a, const unsigned* b)
{
    asm volatile(
        "mma.sync.aligned.m16n8k16.row.col.f32.bf16.bf16.f32 "
        "{%0,%1,%2,%3},{%4,%5,%6,%7},{%8,%9},{%0,%1,%2,%3};"
        : "+f"(d[0]), "+f"(d[1]), "+f"(d[2]), "+f"(d[3])
        : "r"(a[0]), "r"(a[1]), "r"(a[2]), "r"(a[3]), "r"(b[0]), "r"(b[1]));
}

// ---------------- K1: xc = node_feat @ conv_w  (4096x512x64) ----------------
__global__ __launch_bounds__(256) void k_gemm_xc(const float* __restrict__ X,
                                                 const float* __restrict__ W)
{
    const int m0 = blockIdx.x * 64;
    __shared__ float As[16][68];
    __shared__ float Bs[16][64];
    const int tid = threadIdx.x;
    const int tx = tid & 15, ty = tid >> 4;
    const int ar = tid >> 2, ac = (tid & 3) << 2;
    const int br = tid >> 4, bc = (tid & 15) << 2;
    float acc[4][4] = {};
    const float* Ap = X + (m0 + ar) * FEATD;
    float4 aP = *(const float4*)(Ap + ac);
    float4 bP = *(const float4*)(W + br * 64 + bc);
    for (int k0 = 0; k0 < FEATD; k0 += 16) {
        As[ac+0][ar]=aP.x; As[ac+1][ar]=aP.y; As[ac+2][ar]=aP.z; As[ac+3][ar]=aP.w;
        *(float4*)&Bs[br][bc] = bP;
        __syncthreads();
        int kn = k0 + 16;
        if (kn < FEATD) {
            aP = *(const float4*)(Ap + kn + ac);
            bP = *(const float4*)(W + (kn + br) * 64 + bc);
        }
        #pragma unroll
        for (int kk = 0; kk < 16; kk++) {
            float4 a = *(const float4*)&As[kk][ty<<2];
            float4 b = *(const float4*)&Bs[kk][tx<<2];
            float av[4]={a.x,a.y,a.z,a.w}, bv[4]={b.x,b.y,b.z,b.w};
            #pragma unroll
            for (int i=0;i<4;i++)
                #pragma unroll
                for (int j=0;j<4;j++) acc[i][j] += av[i]*bv[j];
        }
        __syncthreads();
    }
    #pragma unroll
    for (int i=0;i<4;i++)
        #pragma unroll
        for (int j=0;j<4;j++)
            g_xc[(m0 + (ty<<2) + i)*DD + (tx<<2) + j] = acc[i][j];
}

// ---------------- K0: init y = xc + conv_b, zero accumulators ----------------
__global__ void k_init(const float* __restrict__ conv_b)
{
    int idx = blockIdx.x*blockDim.x + threadIdx.x;
    if (idx < NN*DD) g_y[idx] = g_xc[idx] + conv_b[idx & 63];
    if (idx < NN) g_dg[idx] = 0.f;
    if (idx < DD) { g_bnsum[idx]=0.f; g_bnsq[idx]=0.f; }
    if (idx < KCLU*DD) g_pool[idx]=0.f;
    if (idx < KCLU*KCLU) g_ssm[idx]=0.f;
    if (idx == 0) { g_num=0.f; g_den=0.f; }
}

// ---------------- K1b: transpose + split xc -> bf16 hi/lo [64][4096] ----------------
__global__ __launch_bounds__(256) void k_xcT()
{
    __shared__ float T[64][65];
    const int m0 = blockIdx.x * 64;
    const int tid = threadIdx.x;
    for (int i = tid; i < 64*64; i += 256) {
        int r = i >> 6, c = i & 63;
        T[r][c] = g_xc[(m0 + r)*DD + c];
    }
    __syncthreads();
    for (int i = tid; i < 64*64; i += 256) {
        int n = i >> 6, m = i & 63;
        float v = T[m][n];
        __nv_bfloat16 h = __float2bfloat16_rn(v);
        g_xcT_h[(size_t)n*NN + m0 + m] = h;
        g_xcT_l[(size_t)n*NN + m0 + m] = __float2bfloat16_rn(v - __bfloat162float(h));
    }
}

// ---------------- PASS1: y += adj @ xc (tensor, 3-product) + degrees -- r3 proven ----
__global__ __launch_bounds__(256) void k_pass1(const float* __restrict__ adj)
{
    const int m0  = blockIdx.x * 64;
    const int kc0 = blockIdx.y * KC;
    __shared__ __nv_bfloat16 Ah[64][24], Al[64][24], Bh[64][24], Bl[64][24];
    const int tid = threadIdx.x;
    const int lane = tid & 31, wid = tid >> 5;
    const int warpM = wid & 1, warpN = wid >> 1;
    const int fr = lane >> 2, kp = (lane & 3) << 1;
    const int ar = tid >> 2, ac4 = tid & 3;
    const int bn = (tid & 127) >> 1, bhalf = tid & 1;

    const float* ap = adj + (size_t)(m0 + ar) * NN + kc0 + ac4 * 4;
    const __nv_bfloat16* bp = (tid < 128 ? g_xcT_h : g_xcT_l) + (size_t)bn * NN + kc0 + bhalf * 8;

    float D[2][2][4] = {};
    float dsum = 0.f;
    float4 pa = *(const float4*)ap;
    uint4  pb = *(const uint4*)bp;

    for (int it = 0; it < NIT; it++) {
        float v[4] = {pa.x, pa.y, pa.z, pa.w};
        union { __nv_bfloat16 h[4]; uint2 u; } uh, ul;
        #pragma unroll
        for (int j = 0; j < 4; j++) {
            __nv_bfloat16 hh = __float2bfloat16_rn(v[j]);
            uh.h[j] = hh;
            ul.h[j] = __float2bfloat16_rn(v[j] - __bfloat162float(hh));
            dsum += v[j];
        }
        *(uint2*)&Ah[ar][ac4*4] = uh.u;
        *(uint2*)&Al[ar][ac4*4] = ul.u;
        if (tid < 128) *(uint4*)&Bh[bn][bhalf*8] = pb;
        else           *(uint4*)&Bl[bn][bhalf*8] = pb;
        __syncthreads();
        if (it + 1 < NIT) {
            ap += 16; bp += 16;
            pa = *(const float4*)ap;
            pb = *(const uint4*)bp;
        }
        unsigned a_h[2][4], a_l[2][4];
        #pragma unroll
        for (int mi = 0; mi < 2; mi++) {
            int row = warpM*32 + mi*16 + fr;
            a_h[mi][0] = *(const unsigned*)&Ah[row][kp];
            a_h[mi][1] = *(const unsigned*)&Ah[row+8][kp];
            a_h[mi][2] = *(const unsigned*)&Ah[row][kp+8];
            a_h[mi][3] = *(const unsigned*)&Ah[row+8][kp+8];
            a_l[mi][0] = *(const unsigned*)&Al[row][kp];
            a_l[mi][1] = *(const unsigned*)&Al[row+8][kp];
            a_l[mi][2] = *(const unsigned*)&Al[row][kp+8];
            a_l[mi][3] = *(const unsigned*)&Al[row+8][kp+8];
        }
        unsigned b_h[2][2], b_l[2][2];
        #pragma unroll
        for (int nj = 0; nj < 2; nj++) {
            int n = warpN*16 + nj*8 + fr;
            b_h[nj][0] = *(const unsigned*)&Bh[n][kp];
            b_h[nj][1] = *(const unsigned*)&Bh[n][kp+8];
            b_l[nj][0] = *(const unsigned*)&Bl[n][kp];
            b_l[nj][1] = *(const unsigned*)&Bl[n][kp+8];
        }
        #pragma unroll
        for (int mi = 0; mi < 2; mi++)
            #pragma unroll
            for (int nj = 0; nj < 2; nj++) {
                mma16816(D[mi][nj], a_h[mi], b_h[nj]);
                mma16816(D[mi][nj], a_h[mi], b_l[nj]);
                mma16816(D[mi][nj], a_l[mi], b_h[nj]);
            }
        __syncthreads();
    }
    atomicAdd(&g_dg[m0 + ar], dsum);
    #pragma unroll
    for (int mi = 0; mi < 2; mi++)
        #pragma unroll
        for (int nj = 0; nj < 2; nj++) {
            int m = m0 + warpM*32 + mi*16 + (lane >> 2);
            int n = warpN*16 + nj*8 + ((lane & 3) << 1);
            atomicAdd(&g_y[m*DD + n],       D[mi][nj][0]);
            atomicAdd(&g_y[m*DD + n + 1],   D[mi][nj][1]);
            atomicAdd(&g_y[(m+8)*DD + n],   D[mi][nj][2]);
            atomicAdd(&g_y[(m+8)*DD + n+1], D[mi][nj][3]);
        }
}

// ---------------- K3a: BN statistics over 4096 rows ----------------
__global__ void k_bnstats()
{
    __shared__ float sh [256];
    __shared__ float sh2[256];
    int tid = threadIdx.x;
    int ch = tid & 63;
    int base = blockIdx.x * 64;
    float s = 0.f, q = 0.f;
    for (int r = base + (tid >> 6); r < base + 64; r += 4) {
        float v = g_y[r*DD + ch];
        s += v; q += v*v;
    }
    sh[tid] = s; sh2[tid] = q;
    __syncthreads();
    if (tid < 64) {
        s = sh[tid] + sh[tid+64] + sh[tid+128] + sh[tid+192];
        q = sh2[tid] + sh2[tid+64] + sh2[tid+128] + sh2[tid+192];
        atomicAdd(&g_bnsum[tid], s);
        atomicAdd(&g_bnsq[tid], q);
    }
}

// ---------------- K3b: warp-per-row BN + L2norm + pool softmax + den + s^T ----------------
// grid 512 (one row per warp, 8 rows/block); pool_w staged in smem.
__global__ __launch_bounds__(256) void k_rowops(const float* __restrict__ bn_g,
                                                const float* __restrict__ bn_b,
                                                const float* __restrict__ pool_w,
                                                const float* __restrict__ pool_b)
{
    __shared__ float pw[6432];
    const int tid = threadIdx.x;
    const int lane = tid & 31, wid = tid >> 5;
    for (int i = tid; i < 6400; i += 256) pw[i] = pool_w[i];
    float mean0 = g_bnsum[lane]      * (1.0f/NN);
    float mean1 = g_bnsum[lane+32]   * (1.0f/NN);
    float rs0 = rsqrtf(g_bnsq[lane]    * (1.0f/NN) - mean0*mean0 + 1e-5f) * bn_g[lane];
    float rs1 = rsqrtf(g_bnsq[lane+32] * (1.0f/NN) - mean1*mean1 + 1e-5f) * bn_g[lane+32];
    float bb0 = bn_b[lane], bb1 = bn_b[lane+32];
    float pb[4];
    #pragma unroll
    for (int b = 0; b < 4; b++) {
        int c = lane + 32*b;
        pb[b] = (c < KCLU) ? pool_b[c] : 0.f;
    }
    __syncthreads();
    const int row = blockIdx.x*8 + wid;
    float v0 = (g_y[row*DD + lane]      - mean0) * rs0 + bb0;
    float v1 = (g_y[row*DD + lane + 32] - mean1) * rs1 + bb1;
    float sq = v0*v0 + v1*v1;
    #pragma unroll
    for (int off = 16; off; off >>= 1) sq += __shfl_xor_sync(0xffffffffu, sq, off);
    float inv = 1.0f / fmaxf(sqrtf(sq), 1e-12f);
    float yn0 = v0 * inv, yn1 = v1 * inv;
    g_yn[row*DD + lane]      = yn0;
    g_yn[row*DD + lane + 32] = yn1;
    float lg[4] = {0.f, 0.f, 0.f, 0.f};
    #pragma unroll 8
    for (int d = 0; d < 64; d++) {
        float yd = __shfl_sync(0xffffffffu, (d < 32) ? yn0 : yn1, d & 31);
        const float* pr = pw + d*100 + lane;
        lg[0] += yd * pr[0];
        lg[1] += yd * pr[32];
        lg[2] += yd * pr[64];
        lg[3] += yd * pr[96];   // valid only for lane<4 (c<100); else discarded
    }
    #pragma unroll
    for (int b = 0; b < 4; b++) lg[b] += pb[b];
    float mx = fmaxf(fmaxf(lg[0], lg[1]), lg[2]);
    if (lane < 4) mx = fmaxf(mx, lg[3]);
    #pragma unroll
    for (int off = 16; off; off >>= 1) mx = fmaxf(mx, __shfl_xor_sync(0xffffffffu, mx, off));
    float e0 = expf(lg[0]-mx), e1 = expf(lg[1]-mx), e2 = expf(lg[2]-mx);
    float e3 = (lane < 4) ? expf(lg[3]-mx) : 0.f;
    float sum = e0+e1+e2+e3;
    #pragma unroll
    for (int off = 16; off; off >>= 1) sum += __shfl_xor_sync(0xffffffffu, sum, off);
    float is = 1.0f / sum;
    float p0 = e0*is, p1 = e1*is, p2 = e2*is, p3 = e3*is;
    g_s[row*SPAD + lane]      = p0;
    g_s[row*SPAD + lane + 32] = p1;
    g_s[row*SPAD + lane + 64] = p2;
    g_s[row*SPAD + lane + 96] = p3;
    g_sT_h[(size_t)(lane)     *NN + row] = __float2bfloat16_rn(p0);
    g_sT_h[(size_t)(lane + 32)*NN + row] = __float2bfloat16_rn(p1);
    g_sT_h[(size_t)(lane + 64)*NN + row] = __float2bfloat16_rn(p2);
    g_sT_h[(size_t)(lane + 96)*NN + row] = __float2bfloat16_rn(p3);
    float s2 = p0*p0 + p1*p1 + p2*p2 + p3*p3;
    #pragma unroll
    for (int off = 16; off; off >>= 1) s2 += __shfl_xor_sync(0xffffffffu, s2, off);
    if (lane == 0) atomicAdd(&g_den, g_dg[row] * s2);
}

// ---------------- PASS2: num = <s, adj @ s> (tensor, single bf16) -- r3 proven ----------------
__global__ __launch_bounds__(256) void k_pass2(const float* __restrict__ adj)
{
    const int m0  = blockIdx.x * 64;
    const int kc0 = blockIdx.y * KC;
    __shared__ __nv_bfloat16 Ah[64][24], Sh[128][24];
    __shared__ float red[256];
    const int tid = threadIdx.x;
    const int lane = tid & 31, wid = tid >> 5;
    const int warpM = wid & 1, warpN = wid >> 1;
    const int fr = lane >> 2, kp = (lane & 3) << 1;
    const int ar = tid >> 2, ac4 = tid & 3;
    const int sn = tid >> 1, shalf = tid & 1;

    const float* ap = adj + (size_t)(m0 + ar) * NN + kc0 + ac4 * 4;
    const __nv_bfloat16* sp = g_sT_h + (size_t)sn * NN + kc0 + shalf * 8;

    float D[2][4][4] = {};
    float4 pa = *(const float4*)ap;
    uint4  ps = *(const uint4*)sp;

    for (int it = 0; it < NIT; it++) {
        float v[4] = {pa.x, pa.y, pa.z, pa.w};
        union { __nv_bfloat16 h[4]; uint2 u; } uh;
        #pragma unroll
        for (int j = 0; j < 4; j++) uh.h[j] = __float2bfloat16_rn(v[j]);
        *(uint2*)&Ah[ar][ac4*4] = uh.u;
        *(uint4*)&Sh[sn][shalf*8] = ps;
        __syncthreads();
        if (it + 1 < NIT) {
            ap += 16; sp += 16;
            pa = *(const float4*)ap;
            ps = *(const uint4*)sp;
        }
        unsigned a_h[2][4];
        #pragma unroll
        for (int mi = 0; mi < 2; mi++) {
            int row = warpM*32 + mi*16 + fr;
            a_h[mi][0] = *(const unsigned*)&Ah[row][kp];
            a_h[mi][1] = *(const unsigned*)&Ah[row+8][kp];
            a_h[mi][2] = *(const unsigned*)&Ah[row][kp+8];
            a_h[mi][3] = *(const unsigned*)&Ah[row+8][kp+8];
        }
        unsigned b_s[4][2];
        #pragma unroll
        for (int nj = 0; nj < 4; nj++) {
            int n = warpN*32 + nj*8 + fr;
            b_s[nj][0] = *(const unsigned*)&Sh[n][kp];
            b_s[nj][1] = *(const unsigned*)&Sh[n][kp+8];
        }
        #pragma unroll
        for (int mi = 0; mi < 2; mi++)
            #pragma unroll
            for (int nj = 0; nj < 4; nj++)
                mma16816(D[mi][nj], a_h[mi], b_s[nj]);
        __syncthreads();
    }
    float part = 0.f;
    #pragma unroll
    for (int mi = 0; mi < 2; mi++)
        #pragma unroll
        for (int nj = 0; nj < 4; nj++) {
            int m = m0 + warpM*32 + mi*16 + (lane >> 2);
            int n = warpN*32 + nj*8 + ((lane & 3) << 1);
            part += D[mi][nj][0]*g_s[m*SPAD + n]     + D[mi][nj][1]*g_s[m*SPAD + n + 1]
                  + D[mi][nj][2]*g_s[(m+8)*SPAD + n] + D[mi][nj][3]*g_s[(m+8)*SPAD + n + 1];
        }
    red[tid] = part;
    __syncthreads();
    for (int s2 = 128; s2 > 0; s2 >>= 1) { if (tid < s2) red[tid] += red[tid+s2]; __syncthreads(); }
    if (tid == 0) atomicAdd(&g_num, red[0]);
}

// ---------------- K5: pool_out = s^T yn, ss = s^T s (64-row chunks) ----------------
__global__ __launch_bounds__(256) void k_pool_ss()
{
    const int k0 = blockIdx.x * 64;
    __shared__ float Ss[64][SPAD];
    __shared__ float Ys[64][64];
    const int tid = threadIdx.x;
    for (int i = tid; i < 64*32; i += 256) {
        int kr = i >> 5, c = (i & 31) << 2;
        *(float4*)&Ss[kr][c] = *(const float4*)(g_s + (size_t)(k0+kr)*SPAD + c);
    }
    for (int i = tid; i < 64*16; i += 256) {
        int kr = i >> 4, c = (i & 15) << 2;
        *(float4*)&Ys[kr][c] = *(const float4*)(g_yn + (size_t)(k0+kr)*64 + c);
    }
    __syncthreads();
    for (int g = tid; g < KCLU*41; g += 256) {
        int m = g / 41;
        int j = (g % 41) * 4;
        const float* cp; int st; float* dst;
        if (j < 64) { cp = &Ys[0][j]; st = 64;   dst = &g_pool[m*DD + j]; }
        else        { cp = &Ss[0][j-64]; st = SPAD; dst = &g_ssm[m*KCLU + (j-64)]; }
        float a0=0.f,a1=0.f,a2=0.f,a3=0.f;
        #pragma unroll 8
        for (int kk = 0; kk < 64; kk++) {
            float sm = Ss[kk][m];
            float4 c = *(const float4*)(cp + kk*st);
            a0 += sm*c.x; a1 += sm*c.y; a2 += sm*c.z; a3 += sm*c.w;
        }
        atomicAdd(dst+0, a0); atomicAdd(dst+1, a1);
        atomicAdd(dst+2, a2); atomicAdd(dst+3, a3);
    }
}

// ---------------- K6: build token + LN1(l=0) + QKV(l=0); block 0 writes losses ----
__global__ __launch_bounds__(256) void k_tok0(const float* __restrict__ cls,
                                              const float* __restrict__ ln_g,
                                              const float* __restrict__ ln_b,
                                              const float* __restrict__ w,
                                              const float* __restrict__ b,
                                              float* __restrict__ out)
{
    const int row = blockIdx.x;
    const int tid = threadIdx.x;
    __shared__ float hs[64];
    __shared__ float red[64];
    __shared__ float r1[256], r2[256];
    float v = 0.f;
    if (tid < 64) {
        v = (row == 0) ? cls[tid] : g_pool[(row-1)*DD + tid];
        g_t[row*DD + tid] = v;
        red[tid] = v;
    }
    __syncthreads();
    for (int s2 = 32; s2 > 0; s2 >>= 1) { if (tid < s2) red[tid] += red[tid+s2]; __syncthreads(); }
    float mean = red[0] * (1.0f/64);
    __syncthreads();
    if (tid < 64) { float d = v - mean; red[tid] = d*d; }
    __syncthreads();
    for (int s2 = 32; s2 > 0; s2 >>= 1) { if (tid < s2) red[tid] += red[tid+s2]; __syncthreads(); }
    float var = red[0] * (1.0f/64);
    __syncthreads();
    if (tid < 64)
        hs[tid] = (v - mean) * rsqrtf(var + 1e-6f) * ln_g[tid] + ln_b[tid];
    __syncthreads();
    if (tid < 192) {
        float a = b[tid];
        const float* wp = w + tid;
        #pragma unroll 8
        for (int d = 0; d < 64; d++) a += hs[d] * wp[d*192];
        g_qkvb[0][row*192 + tid] = a;
    }
    if (row == 0) {
        float sq = 0.f, tr = 0.f;
        for (int i = tid; i < KCLU*KCLU; i += 256) {
            float x = g_ssm[i];
            sq += x*x;
            if (i % (KCLU+1) == 0) tr += x;
        }
        r1[tid] = sq; r2[tid] = tr;
        __syncthreads();
        for (int s2 = 128; s2 > 0; s2 >>= 1) { if (tid < s2) { r1[tid]+=r1[tid+s2]; r2[tid]+=r2[tid+s2]; } __syncthreads(); }
        if (tid == 0) {
            float f = sqrtf(r1[0]);
            out[2] = -(g_num / g_den);
            out[3] = sqrtf(fmaxf(2.0f - r2[0] / (5.0f * f), 0.0f));
        }
    }
}

// ---------------- K7: attn + proj + LN2 + FC1 + GELU + FC2, then next LN1+QKV or head ----
__global__ __launch_bounds__(256) void k_fused(const float* __restrict__ proj_w,
                                               const float* __restrict__ proj_b,
                                               const float* __restrict__ ln2_g,
                                               const float* __restrict__ ln2_b,
                                               const float* __restrict__ fc1_w,
                                               const float* __restrict__ fc1_b,
                                               const float* __restrict__ fc2_w,
                                               const float* __restrict__ fc2_b,
                                               const float* __restrict__ ln1_g,
                                               const float* __restrict__ ln1_b,
                                               const float* __restrict__ qkv_w,
                                               const float* __restrict__ qkv_b,
                                               const float* __restrict__ norm_g,
                                               const float* __restrict__ norm_b,
                                               const float* __restrict__ head_w,
                                               const float* __restrict__ head_b,
                                               float* __restrict__ out,
                                               int l, int final_flag)
{
    const int row = blockIdx.x;
    const int tid = threadIdx.x;
    const int lane = tid & 31, wid = tid >> 5;
    const float* qin = g_qkvb[l & 1];
    float*       qout = g_qkvb[(l + 1) & 1];
    __shared__ float osm[64];
    __shared__ float hs[64];
    __shared__ float red[64];
    __shared__ float h1s[256];

    {
        const int h8 = wid * 8;
        float qv[8];
        #pragma unroll
        for (int d = 0; d < 8; d++) qv[d] = qin[row*192 + h8 + d];
        float sc[4];
        #pragma unroll
        for (int i = 0; i < 4; i++) {
            int j = lane + 32*i;
            float s = -3.0e38f;
            if (j < TOK) {
                const float* kp = qin + j*192 + 64 + h8;
                s = 0.f;
                #pragma unroll
                for (int d = 0; d < 8; d++) s += qv[d]*kp[d];
                s *= 0.35355339059327373f;
            }
            sc[i] = s;
        }
        float mx = fmaxf(fmaxf(sc[0],sc[1]), fmaxf(sc[2],sc[3]));
        #pragma unroll
        for (int off=16; off; off>>=1) mx = fmaxf(mx, __shfl_xor_sync(0xffffffffu, mx, off));
        float es[4]; float sum = 0.f;
        #pragma unroll
        for (int i = 0; i < 4; i++) {
            int j = lane + 32*i;
            es[i] = (j < TOK) ? expf(sc[i] - mx) : 0.f;
            sum += es[i];
        }
        #pragma unroll
        for (int off=16; off; off>>=1) sum += __shfl_xor_sync(0xffffffffu, sum, off);
        float inv = 1.0f / sum;
        float acc[8] = {};
        #pragma unroll
        for (int i = 0; i < 4; i++) {
            int j = lane + 32*i;
            if (j < TOK) {
                float p = es[i] * inv;
                const float* vp = qin + j*192 + 128 + h8;
                #pragma unroll
                for (int d = 0; d < 8; d++) acc[d] += p * vp[d];
            }
        }
        #pragma unroll
        for (int d = 0; d < 8; d++) {
            #pragma unroll
            for (int off=16; off; off>>=1) acc[d] += __shfl_xor_sync(0xffffffffu, acc[d], off);
        }
        if (lane == 0) {
            #pragma unroll
            for (int d = 0; d < 8; d++) osm[h8 + d] = acc[d];
        }
    }
    __syncthreads();

    float tnew = 0.f;
    if (tid < 64) {
        float a = proj_b[l*64 + tid];
        const float* wp = proj_w + (size_t)l*64*64 + tid;
        #pragma unroll 8
        for (int k = 0; k < 64; k++) a += osm[k] * wp[k*64];
        tnew = g_t[row*DD + tid] + a;
        red[tid] = tnew;
    }
    __syncthreads();
    for (int s2 = 32; s2 > 0; s2 >>= 1) { if (tid < s2) red[tid] += red[tid+s2]; __syncthreads(); }
    float mean = red[0] * (1.0f/64);
    __syncthreads();
    if (tid < 64) { float d = tnew - mean; red[tid] = d*d; }
    __syncthreads();
    for (int s2 = 32; s2 > 0; s2 >>= 1) { if (tid < s2) red[tid] += red[tid+s2]; __syncthreads(); }
    float var = red[0] * (1.0f/64);
    __syncthreads();
    if (tid < 64)
        hs[tid] = (tnew - mean) * rsqrtf(var + 1e-6f) * ln2_g[l*64 + tid] + ln2_b[l*64 + tid];
    __syncthreads();

    {
        float a = fc1_b[l*256 + tid];
        const float* wp = fc1_w + (size_t)l*64*256 + tid;
        #pragma unroll 8
        for (int d = 0; d < 64; d++) a += hs[d] * wp[d*256];
        h1s[tid] = 0.5f * a * (1.0f + erff(a * 0.7071067811865475f));
    }
    __syncthreads();

    float tfin = 0.f;
    if (tid < 64) {
        float a = fc2_b[l*64 + tid];
        const float* wp = fc2_w + (size_t)l*256*64 + tid;
        #pragma unroll 8
        for (int k = 0; k < 256; k++) a += h1s[k] * wp[k*64];
        tfin = tnew + a;
        red[tid] = tfin;
    }
    __syncthreads();
    for (int s2 = 32; s2 > 0; s2 >>= 1) { if (tid < s2) red[tid] += red[tid+s2]; __syncthreads(); }
    float mean2 = red[0] * (1.0f/64);
    __syncthreads();
    if (tid < 64) { float d = tfin - mean2; red[tid] = d*d; }
    __syncthreads();
    for (int s2 = 32; s2 > 0; s2 >>= 1) { if (tid < s2) red[tid] += red[tid+s2]; __syncthreads(); }
    float var2 = red[0] * (1.0f/64);
    __syncthreads();

    if (!final_flag) {
        if (tid < 64) {
            g_t[row*DD + tid] = tfin;
            hs[tid] = (tfin - mean2) * rsqrtf(var2 + 1e-6f) * ln1_g[(l+1)*64 + tid] + ln1_b[(l+1)*64 + tid];
        }
        __syncthreads();
        if (tid < 192) {
            float a = qkv_b[(l+1)*192 + tid];
            const float* wp = qkv_w + (size_t)(l+1)*64*192 + tid;
            #pragma unroll 8
            for (int d = 0; d < 64; d++) a += hs[d] * wp[d*192];
            qout[row*192 + tid] = a;
        }
    } else {
        float h = 0.f;
        if (tid < 64)
            h = (tfin - mean2) * rsqrtf(var2 + 1e-6f) * norm_g[tid] + norm_b[tid];
        #pragma unroll
        for (int c = 0; c < 2; c++) {
            if (tid < 64) red[tid] = h * head_w[tid*2 + c];
            __syncthreads();
            for (int s2 = 32; s2 > 0; s2 >>= 1) { if (tid < s2) red[tid] += red[tid+s2]; __syncthreads(); }
            if (tid == 0) out[c] = red[0] + head_b[c];
            __syncthreads();
        }
    }
}

// ---------------- launcher ----------------
extern "C" void kernel_launch(void* const* d_in, const int* in_sizes, int n_in,
                              void* d_out, int out_size)
{
    const float* node   = (const float*)d_in[0];
    const float* adj    = (const float*)d_in[1];
    const float* conv_w = (const float*)d_in[2];
    const float* conv_b = (const float*)d_in[3];
    const float* bn_g   = (const float*)d_in[4];
    const float* bn_b   = (const float*)d_in[5];
    const float* pool_w = (const float*)d_in[6];
    const float* pool_b = (const float*)d_in[7];
    const float* cls    = (const float*)d_in[8];
    const float* ln1_g  = (const float*)d_in[9];
    const float* ln1_b  = (const float*)d_in[10];
    const float* qkv_w  = (const float*)d_in[11];
    const float* qkv_b  = (const float*)d_in[12];
    const float* proj_w = (const float*)d_in[13];
    const float* proj_b = (const float*)d_in[14];
    const float* ln2_g  = (const float*)d_in[15];
    const float* ln2_b  = (const float*)d_in[16];
    const float* fc1_w  = (const float*)d_in[17];
    const float* fc1_b  = (const float*)d_in[18];
    const float* fc2_w  = (const float*)d_in[19];
    const float* fc2_b  = (const float*)d_in[20];
    const float* norm_g = (const float*)d_in[21];
    const float* norm_b = (const float*)d_in[22];
    const float* head_w = (const float*)d_in[23];
    const float* head_b = (const float*)d_in[24];
    float* out = (float*)d_out;

    k_gemm_xc<<<NN/64, 256>>>(node, conv_w);
    k_init<<<(NN*DD)/256, 256>>>(conv_b);
    k_xcT<<<NN/64, 256>>>();
    k_pass1<<<dim3(NN/64, KSPLIT), 256>>>(adj);
    k_bnstats<<<NN/64, 256>>>();
    k_rowops<<<NN/8, 256>>>(bn_g, bn_b, pool_w, pool_b);
    k_pass2<<<dim3(NN/64, KSPLIT), 256>>>(adj);
    k_pool_ss<<<NN/64, 256>>>();
    k_tok0<<<TOK, 256>>>(cls, ln1_g, ln1_b, qkv_w, qkv_b, out);
    k_fused<<<TOK, 256>>>(proj_w, proj_b, ln2_g, ln2_b, fc1_w, fc1_b, fc2_w, fc2_b,
                          ln1_g, ln1_b, qkv_w, qkv_b, norm_g, norm_b, head_w, head_b,
                          out, 0, 0);
    k_fused<<<TOK, 256>>>(proj_w, proj_b, ln2_g, ln2_b, fc1_w, fc1_b, fc2_w, fc2_b,
                          ln1_g, ln1_b, qkv_w, qkv_b, norm_g, norm_b, head_w, head_b,
                          out, 1, 0);
    k_fused<<<1, 256>>>(proj_w, proj_b, ln2_g, ln2_b, fc1_w, fc1_b, fc2_w, fc2_b,
                        ln1_g, ln1_b, qkv_w, qkv_b, norm_g, norm_b, head_w, head_b,
                        out, 2, 1);
}

// round 15
// speedup vs baseline: 1.6071x; 1.0900x over previous
#include <cuda_runtime.h>
#include <cuda_bf16.h>
#include <math.h>

#define NN    4096
#define FEATD 512
#define DD    64
#define KCLU  100
#define SPAD  128
#define TOK   101
#define LNUM  3
#define KSPLIT 16
#define KC    (NN / KSPLIT)     // 256
#define NIT   (KC / 16)         // 16
#define PSPLIT 32
#define KC2   (NN / PSPLIT)     // 128
#define NIT2  (KC2 / 16)        // 8

// ---------------- device scratch (no allocation allowed) ----------------
__device__ float g_xc[NN*DD];
__device__ float g_y [NN*DD];
__device__ float g_yn[NN*DD];
__device__ float g_dg[NN];
__device__ float g_bnsum[DD];
__device__ float g_bnsq [DD];
__device__ float g_s[NN*SPAD];
__device__ float g_num;
__device__ float g_den;
__device__ float g_pool[KCLU*DD];
__device__ float g_ssm [KCLU*KCLU];
__device__ float g_t  [TOK*DD];
__device__ float g_qkvb[2][TOK*192];
__device__ __nv_bfloat16 g_xcT_h[DD*NN];   // xc^T hi  [64][4096]
__device__ __nv_bfloat16 g_xcT_l[DD*NN];   // xc^T lo
__device__ __nv_bfloat16 g_sT_h [SPAD*NN]; // s^T hi  [128][4096] (rows >=100 zero)
__device__ __nv_bfloat16 g_sT_l [SPAD*NN]; // s^T lo
__device__ __nv_bfloat16 g_ynT_h[DD*NN];   // yn^T hi [64][4096]
__device__ __nv_bfloat16 g_ynT_l[DD*NN];   // yn^T lo

// ---------------- bf16 MMA helper (m16n8k16, fp32 accum) ----------------
__device__ __forceinline__ void mma16816(float* d, const unsigned* a, const unsigned* b)
{
    asm volatile(
        "mma.sync.aligned.m16n8k16.row.col.f32.bf16.bf16.f32 "
        "{%0,%1,%2,%3},{%4,%5,%6,%7},{%8,%9},{%0,%1,%2,%3};"
        : "+f"(d[0]), "+f"(d[1]), "+f"(d[2]), "+f"(d[3])
        : "r"(a[0]), "r"(a[1]), "r"(a[2]), "r"(a[3]), "r"(b[0]), "r"(b[1]));
}

// ---------------- K1: xc = node_feat @ conv_w  (4096x512x64) ----------------
__global__ __launch_bounds__(256) void k_gemm_xc(const float* __restrict__ X,
                                                 const float* __restrict__ W)
{
    const int m0 = blockIdx.x * 64;
    __shared__ float As[16][68];
    __shared__ float Bs[16][64];
    const int tid = threadIdx.x;
    const int tx = tid & 15, ty = tid >> 4;
    const int ar = tid >> 2, ac = (tid & 3) << 2;
    const int br = tid >> 4, bc = (tid & 15) << 2;
    float acc[4][4] = {};
    const float* Ap = X + (m0 + ar) * FEATD;
    float4 aP = *(const float4*)(Ap + ac);
    float4 bP = *(const float4*)(W + br * 64 + bc);
    for (int k0 = 0; k0 < FEATD; k0 += 16) {
        As[ac+0][ar]=aP.x; As[ac+1][ar]=aP.y; As[ac+2][ar]=aP.z; As[ac+3][ar]=aP.w;
        *(float4*)&Bs[br][bc] = bP;
        __syncthreads();
        int kn = k0 + 16;
        if (kn < FEATD) {
            aP = *(const float4*)(Ap + kn + ac);
            bP = *(const float4*)(W + (kn + br) * 64 + bc);
        }
        #pragma unroll
        for (int kk = 0; kk < 16; kk++) {
            float4 a = *(const float4*)&As[kk][ty<<2];
            float4 b = *(const float4*)&Bs[kk][tx<<2];
            float av[4]={a.x,a.y,a.z,a.w}, bv[4]={b.x,b.y,b.z,b.w};
            #pragma unroll
            for (int i=0;i<4;i++)
                #pragma unroll
                for (int j=0;j<4;j++) acc[i][j] += av[i]*bv[j];
        }
        __syncthreads();
    }
    #pragma unroll
    for (int i=0;i<4;i++)
        #pragma unroll
        for (int j=0;j<4;j++)
            g_xc[(m0 + (ty<<2) + i)*DD + (tx<<2) + j] = acc[i][j];
}

// ---------------- K0: init y = xc + conv_b, zero accumulators ----------------
__global__ void k_init(const float* __restrict__ conv_b)
{
    int idx = blockIdx.x*blockDim.x + threadIdx.x;
    if (idx < NN*DD) g_y[idx] = g_xc[idx] + conv_b[idx & 63];
    if (idx < NN) g_dg[idx] = 0.f;
    if (idx < DD) { g_bnsum[idx]=0.f; g_bnsq[idx]=0.f; }
    if (idx < KCLU*DD) g_pool[idx]=0.f;
    if (idx < KCLU*KCLU) g_ssm[idx]=0.f;
    if (idx == 0) { g_num=0.f; g_den=0.f; }
}

// ---------------- K1b: transpose + split xc -> bf16 hi/lo [64][4096] ----------------
__global__ __launch_bounds__(256) void k_xcT()
{
    __shared__ float T[64][65];
    const int m0 = blockIdx.x * 64;
    const int tid = threadIdx.x;
    for (int i = tid; i < 64*64; i += 256) {
        int r = i >> 6, c = i & 63;
        T[r][c] = g_xc[(m0 + r)*DD + c];
    }
    __syncthreads();
    for (int i = tid; i < 64*64; i += 256) {
        int n = i >> 6, m = i & 63;
        float v = T[m][n];
        __nv_bfloat16 h = __float2bfloat16_rn(v);
        g_xcT_h[(size_t)n*NN + m0 + m] = h;
        g_xcT_l[(size_t)n*NN + m0 + m] = __float2bfloat16_rn(v - __bfloat162float(h));
    }
}

// ---------------- PASS1: y += adj @ xc (tensor, 3-product) + degrees -- r3 proven ----
__global__ __launch_bounds__(256) void k_pass1(const float* __restrict__ adj)
{
    const int m0  = blockIdx.x * 64;
    const int kc0 = blockIdx.y * KC;
    __shared__ __nv_bfloat16 Ah[64][24], Al[64][24], Bh[64][24], Bl[64][24];
    const int tid = threadIdx.x;
    const int lane = tid & 31, wid = tid >> 5;
    const int warpM = wid & 1, warpN = wid >> 1;
    const int fr = lane >> 2, kp = (lane & 3) << 1;
    const int ar = tid >> 2, ac4 = tid & 3;
    const int bn = (tid & 127) >> 1, bhalf = tid & 1;

    const float* ap = adj + (size_t)(m0 + ar) * NN + kc0 + ac4 * 4;
    const __nv_bfloat16* bp = (tid < 128 ? g_xcT_h : g_xcT_l) + (size_t)bn * NN + kc0 + bhalf * 8;

    float D[2][2][4] = {};
    float dsum = 0.f;
    float4 pa = *(const float4*)ap;
    uint4  pb = *(const uint4*)bp;

    for (int it = 0; it < NIT; it++) {
        float v[4] = {pa.x, pa.y, pa.z, pa.w};
        union { __nv_bfloat16 h[4]; uint2 u; } uh, ul;
        #pragma unroll
        for (int j = 0; j < 4; j++) {
            __nv_bfloat16 hh = __float2bfloat16_rn(v[j]);
            uh.h[j] = hh;
            ul.h[j] = __float2bfloat16_rn(v[j] - __bfloat162float(hh));
            dsum += v[j];
        }
        *(uint2*)&Ah[ar][ac4*4] = uh.u;
        *(uint2*)&Al[ar][ac4*4] = ul.u;
        if (tid < 128) *(uint4*)&Bh[bn][bhalf*8] = pb;
        else           *(uint4*)&Bl[bn][bhalf*8] = pb;
        __syncthreads();
        if (it + 1 < NIT) {
            ap += 16; bp += 16;
            pa = *(const float4*)ap;
            pb = *(const uint4*)bp;
        }
        unsigned a_h[2][4], a_l[2][4];
        #pragma unroll
        for (int mi = 0; mi < 2; mi++) {
            int row = warpM*32 + mi*16 + fr;
            a_h[mi][0] = *(const unsigned*)&Ah[row][kp];
            a_h[mi][1] = *(const unsigned*)&Ah[row+8][kp];
            a_h[mi][2] = *(const unsigned*)&Ah[row][kp+8];
            a_h[mi][3] = *(const unsigned*)&Ah[row+8][kp+8];
            a_l[mi][0] = *(const unsigned*)&Al[row][kp];
            a_l[mi][1] = *(const unsigned*)&Al[row+8][kp];
            a_l[mi][2] = *(const unsigned*)&Al[row][kp+8];
            a_l[mi][3] = *(const unsigned*)&Al[row+8][kp+8];
        }
        unsigned b_h[2][2], b_l[2][2];
        #pragma unroll
        for (int nj = 0; nj < 2; nj++) {
            int n = warpN*16 + nj*8 + fr;
            b_h[nj][0] = *(const unsigned*)&Bh[n][kp];
            b_h[nj][1] = *(const unsigned*)&Bh[n][kp+8];
            b_l[nj][0] = *(const unsigned*)&Bl[n][kp];
            b_l[nj][1] = *(const unsigned*)&Bl[n][kp+8];
        }
        #pragma unroll
        for (int mi = 0; mi < 2; mi++)
            #pragma unroll
            for (int nj = 0; nj < 2; nj++) {
                mma16816(D[mi][nj], a_h[mi], b_h[nj]);
                mma16816(D[mi][nj], a_h[mi], b_l[nj]);
                mma16816(D[mi][nj], a_l[mi], b_h[nj]);
            }
        __syncthreads();
    }
    atomicAdd(&g_dg[m0 + ar], dsum);
    #pragma unroll
    for (int mi = 0; mi < 2; mi++)
        #pragma unroll
        for (int nj = 0; nj < 2; nj++) {
            int m = m0 + warpM*32 + mi*16 + (lane >> 2);
            int n = warpN*16 + nj*8 + ((lane & 3) << 1);
            atomicAdd(&g_y[m*DD + n],       D[mi][nj][0]);
            atomicAdd(&g_y[m*DD + n + 1],   D[mi][nj][1]);
            atomicAdd(&g_y[(m+8)*DD + n],   D[mi][nj][2]);
            atomicAdd(&g_y[(m+8)*DD + n+1], D[mi][nj][3]);
        }
}

// ---------------- K3a: BN statistics over 4096 rows ----------------
__global__ void k_bnstats()
{
    __shared__ float sh [256];
    __shared__ float sh2[256];
    int tid = threadIdx.x;
    int ch = tid & 63;
    int base = blockIdx.x * 64;
    float s = 0.f, q = 0.f;
    for (int r = base + (tid >> 6); r < base + 64; r += 4) {
        float v = g_y[r*DD + ch];
        s += v; q += v*v;
    }
    sh[tid] = s; sh2[tid] = q;
    __syncthreads();
    if (tid < 64) {
        s = sh[tid] + sh[tid+64] + sh[tid+128] + sh[tid+192];
        q = sh2[tid] + sh2[tid+64] + sh2[tid+128] + sh2[tid+192];
        atomicAdd(&g_bnsum[tid], s);
        atomicAdd(&g_bnsq[tid], q);
    }
}

// ---------------- K3b: warp-per-row BN + L2norm + pool softmax + den + transposed bf16 ----
__global__ __launch_bounds__(256) void k_rowops(const float* __restrict__ bn_g,
                                                const float* __restrict__ bn_b,
                                                const float* __restrict__ pool_w,
                                                const float* __restrict__ pool_b)
{
    __shared__ float pw[6432];
    const int tid = threadIdx.x;
    const int lane = tid & 31, wid = tid >> 5;
    for (int i = tid; i < 6400; i += 256) pw[i] = pool_w[i];
    float mean0 = g_bnsum[lane]      * (1.0f/NN);
    float mean1 = g_bnsum[lane+32]   * (1.0f/NN);
    float rs0 = rsqrtf(g_bnsq[lane]    * (1.0f/NN) - mean0*mean0 + 1e-5f) * bn_g[lane];
    float rs1 = rsqrtf(g_bnsq[lane+32] * (1.0f/NN) - mean1*mean1 + 1e-5f) * bn_g[lane+32];
    float bb0 = bn_b[lane], bb1 = bn_b[lane+32];
    float pb[4];
    #pragma unroll
    for (int b = 0; b < 4; b++) {
        int c = lane + 32*b;
        pb[b] = (c < KCLU) ? pool_b[c] : 0.f;
    }
    __syncthreads();
    const int row = blockIdx.x*8 + wid;
    float v0 = (g_y[row*DD + lane]      - mean0) * rs0 + bb0;
    float v1 = (g_y[row*DD + lane + 32] - mean1) * rs1 + bb1;
    float sq = v0*v0 + v1*v1;
    #pragma unroll
    for (int off = 16; off; off >>= 1) sq += __shfl_xor_sync(0xffffffffu, sq, off);
    float inv = 1.0f / fmaxf(sqrtf(sq), 1e-12f);
    float yn0 = v0 * inv, yn1 = v1 * inv;
    g_yn[row*DD + lane]      = yn0;
    g_yn[row*DD + lane + 32] = yn1;
    {
        __nv_bfloat16 h0 = __float2bfloat16_rn(yn0);
        __nv_bfloat16 h1 = __float2bfloat16_rn(yn1);
        g_ynT_h[(size_t)lane*NN + row]      = h0;
        g_ynT_h[(size_t)(lane+32)*NN + row] = h1;
        g_ynT_l[(size_t)lane*NN + row]      = __float2bfloat16_rn(yn0 - __bfloat162float(h0));
        g_ynT_l[(size_t)(lane+32)*NN + row] = __float2bfloat16_rn(yn1 - __bfloat162float(h1));
    }
    float lg[4] = {0.f, 0.f, 0.f, 0.f};
    #pragma unroll 8
    for (int d = 0; d < 64; d++) {
        float yd = __shfl_sync(0xffffffffu, (d < 32) ? yn0 : yn1, d & 31);
        const float* pr = pw + d*100 + lane;
        lg[0] += yd * pr[0];
        lg[1] += yd * pr[32];
        lg[2] += yd * pr[64];
        lg[3] += yd * pr[96];   // valid only for lane<4 (c<100); else discarded
    }
    #pragma unroll
    for (int b = 0; b < 4; b++) lg[b] += pb[b];
    float mx = fmaxf(fmaxf(lg[0], lg[1]), lg[2]);
    if (lane < 4) mx = fmaxf(mx, lg[3]);
    #pragma unroll
    for (int off = 16; off; off >>= 1) mx = fmaxf(mx, __shfl_xor_sync(0xffffffffu, mx, off));
    float e0 = expf(lg[0]-mx), e1 = expf(lg[1]-mx), e2 = expf(lg[2]-mx);
    float e3 = (lane < 4) ? expf(lg[3]-mx) : 0.f;
    float sum = e0+e1+e2+e3;
    #pragma unroll
    for (int off = 16; off; off >>= 1) sum += __shfl_xor_sync(0xffffffffu, sum, off);
    float is = 1.0f / sum;
    float p[4];
    p[0] = e0*is; p[1] = e1*is; p[2] = e2*is; p[3] = e3*is;
    #pragma unroll
    for (int b = 0; b < 4; b++) {
        g_s[row*SPAD + lane + 32*b] = p[b];
        __nv_bfloat16 h = __float2bfloat16_rn(p[b]);
        g_sT_h[(size_t)(lane + 32*b)*NN + row] = h;
        g_sT_l[(size_t)(lane + 32*b)*NN + row] = __float2bfloat16_rn(p[b] - __bfloat162float(h));
    }
    float s2 = p[0]*p[0] + p[1]*p[1] + p[2]*p[2] + p[3]*p[3];
    #pragma unroll
    for (int off = 16; off; off >>= 1) s2 += __shfl_xor_sync(0xffffffffu, s2, off);
    if (lane == 0) atomicAdd(&g_den, g_dg[row] * s2);
}

// ---------------- PASS2: num = <s, adj @ s> (tensor, single bf16) -- r3 proven ----------------
__global__ __launch_bounds__(256) void k_pass2(const float* __restrict__ adj)
{
    const int m0  = blockIdx.x * 64;
    const int kc0 = blockIdx.y * KC;
    __shared__ __nv_bfloat16 Ah[64][24], Sh[128][24];
    __shared__ float red[256];
    const int tid = threadIdx.x;
    const int lane = tid & 31, wid = tid >> 5;
    const int warpM = wid & 1, warpN = wid >> 1;
    const int fr = lane >> 2, kp = (lane & 3) << 1;
    const int ar = tid >> 2, ac4 = tid & 3;
    const int sn = tid >> 1, shalf = tid & 1;

    const float* ap = adj + (size_t)(m0 + ar) * NN + kc0 + ac4 * 4;
    const __nv_bfloat16* sp = g_sT_h + (size_t)sn * NN + kc0 + shalf * 8;

    float D[2][4][4] = {};
    float4 pa = *(const float4*)ap;
    uint4  ps = *(const uint4*)sp;

    for (int it = 0; it < NIT; it++) {
        float v[4] = {pa.x, pa.y, pa.z, pa.w};
        union { __nv_bfloat16 h[4]; uint2 u; } uh;
        #pragma unroll
        for (int j = 0; j < 4; j++) uh.h[j] = __float2bfloat16_rn(v[j]);
        *(uint2*)&Ah[ar][ac4*4] = uh.u;
        *(uint4*)&Sh[sn][shalf*8] = ps;
        __syncthreads();
        if (it + 1 < NIT) {
            ap += 16; sp += 16;
            pa = *(const float4*)ap;
            ps = *(const uint4*)sp;
        }
        unsigned a_h[2][4];
        #pragma unroll
        for (int mi = 0; mi < 2; mi++) {
            int row = warpM*32 + mi*16 + fr;
            a_h[mi][0] = *(const unsigned*)&Ah[row][kp];
            a_h[mi][1] = *(const unsigned*)&Ah[row+8][kp];
            a_h[mi][2] = *(const unsigned*)&Ah[row][kp+8];
            a_h[mi][3] = *(const unsigned*)&Ah[row+8][kp+8];
        }
        unsigned b_s[4][2];
        #pragma unroll
        for (int nj = 0; nj < 4; nj++) {
            int n = warpN*32 + nj*8 + fr;
            b_s[nj][0] = *(const unsigned*)&Sh[n][kp];
            b_s[nj][1] = *(const unsigned*)&Sh[n][kp+8];
        }
        #pragma unroll
        for (int mi = 0; mi < 2; mi++)
            #pragma unroll
            for (int nj = 0; nj < 4; nj++)
                mma16816(D[mi][nj], a_h[mi], b_s[nj]);
        __syncthreads();
    }
    float part = 0.f;
    #pragma unroll
    for (int mi = 0; mi < 2; mi++)
        #pragma unroll
        for (int nj = 0; nj < 4; nj++) {
            int m = m0 + warpM*32 + mi*16 + (lane >> 2);
            int n = warpN*32 + nj*8 + ((lane & 3) << 1);
            part += D[mi][nj][0]*g_s[m*SPAD + n]     + D[mi][nj][1]*g_s[m*SPAD + n + 1]
                  + D[mi][nj][2]*g_s[(m+8)*SPAD + n] + D[mi][nj][3]*g_s[(m+8)*SPAD + n + 1];
        }
    red[tid] = part;
    __syncthreads();
    for (int s2 = 128; s2 > 0; s2 >>= 1) { if (tid < s2) red[tid] += red[tid+s2]; __syncthreads(); }
    if (tid == 0) atomicAdd(&g_num, red[0]);
}

// ---------------- K5a: pool = s^T @ yn (tensor, 3-product hi/lo) ----------------
// M=128 (100 used), N=64. Warp tile 32m x 32n: warpM in {0..3}, warpN in {0,1}.
__global__ __launch_bounds__(256) void k_poolT()
{
    const int kc0 = blockIdx.x * KC2;
    __shared__ __nv_bfloat16 Ah[128][24], Al[128][24], Bh[64][24], Bl[64][24];
    const int tid = threadIdx.x;
    const int lane = tid & 31, wid = tid >> 5;
    const int warpM = wid & 3, warpN = wid >> 2;
    const int fr = lane >> 2, kp = (lane & 3) << 1;
    const int sn = tid >> 1, shalf = tid & 1;
    const int bn = (tid & 127) >> 1, bhalf = tid & 1;

    const __nv_bfloat16* aph = g_sT_h + (size_t)sn * NN + kc0 + shalf * 8;
    const __nv_bfloat16* apl = g_sT_l + (size_t)sn * NN + kc0 + shalf * 8;
    const __nv_bfloat16* bp  = (tid < 128 ? g_ynT_h : g_ynT_l) + (size_t)bn * NN + kc0 + bhalf * 8;

    float D[2][4][4] = {};
    uint4 pah = *(const uint4*)aph;
    uint4 pal = *(const uint4*)apl;
    uint4 pb  = *(const uint4*)bp;

    for (int it = 0; it < NIT2; it++) {
        *(uint4*)&Ah[sn][shalf*8] = pah;
        *(uint4*)&Al[sn][shalf*8] = pal;
        if (tid < 128) *(uint4*)&Bh[bn][bhalf*8] = pb;
        else           *(uint4*)&Bl[bn][bhalf*8] = pb;
        __syncthreads();
        if (it + 1 < NIT2) {
            aph += 16; apl += 16; bp += 16;
            pah = *(const uint4*)aph;
            pal = *(const uint4*)apl;
            pb  = *(const uint4*)bp;
        }
        unsigned a_h[2][4], a_l[2][4];
        #pragma unroll
        for (int mi = 0; mi < 2; mi++) {
            int row = warpM*32 + mi*16 + fr;
            a_h[mi][0] = *(const unsigned*)&Ah[row][kp];
            a_h[mi][1] = *(const unsigned*)&Ah[row+8][kp];
            a_h[mi][2] = *(const unsigned*)&Ah[row][kp+8];
            a_h[mi][3] = *(const unsigned*)&Ah[row+8][kp+8];
            a_l[mi][0] = *(const unsigned*)&Al[row][kp];
            a_l[mi][1] = *(const unsigned*)&Al[row+8][kp];
            a_l[mi][2] = *(const unsigned*)&Al[row][kp+8];
            a_l[mi][3] = *(const unsigned*)&Al[row+8][kp+8];
        }
        unsigned b_h[4][2], b_l[4][2];
        #pragma unroll
        for (int nj = 0; nj < 4; nj++) {
            int n = warpN*32 + nj*8 + fr;
            b_h[nj][0] = *(const unsigned*)&Bh[n][kp];
            b_h[nj][1] = *(const unsigned*)&Bh[n][kp+8];
            b_l[nj][0] = *(const unsigned*)&Bl[n][kp];
            b_l[nj][1] = *(const unsigned*)&Bl[n][kp+8];
        }
        #pragma unroll
        for (int mi = 0; mi < 2; mi++)
            #pragma unroll
            for (int nj = 0; nj < 4; nj++) {
                mma16816(D[mi][nj], a_h[mi], b_h[nj]);
                mma16816(D[mi][nj], a_h[mi], b_l[nj]);
                mma16816(D[mi][nj], a_l[mi], b_h[nj]);
            }
        __syncthreads();
    }
    #pragma unroll
    for (int mi = 0; mi < 2; mi++)
        #pragma unroll
        for (int nj = 0; nj < 4; nj++) {
            int m = warpM*32 + mi*16 + (lane >> 2);
            int n = warpN*32 + nj*8 + ((lane & 3) << 1);
            if (m < KCLU) {
                atomicAdd(&g_pool[m*DD + n],     D[mi][nj][0]);
                atomicAdd(&g_pool[m*DD + n + 1], D[mi][nj][1]);
            }
            if (m + 8 < KCLU) {
                atomicAdd(&g_pool[(m+8)*DD + n],     D[mi][nj][2]);
                atomicAdd(&g_pool[(m+8)*DD + n + 1], D[mi][nj][3]);
            }
        }
}

// ---------------- K5b: ss = s^T @ s (tensor, 3-product hi/lo) ----------------
// M=128, N=128 (100x100 used). A and B operands are the same sT tiles.
__global__ __launch_bounds__(256) void k_ssT()
{
    const int kc0 = blockIdx.x * KC2;
    __shared__ __nv_bfloat16 Sh[128][24], Sl[128][24];
    const int tid = threadIdx.x;
    const int lane = tid & 31, wid = tid >> 5;
    const int warpM = wid & 3, warpN = wid >> 2;   // 4 x 2: 32 rows x 64 cols per warp
    const int fr = lane >> 2, kp = (lane & 3) << 1;
    const int sn = tid >> 1, shalf = tid & 1;

    const __nv_bfloat16* sph = g_sT_h + (size_t)sn * NN + kc0 + shalf * 8;
    const __nv_bfloat16* spl = g_sT_l + (size_t)sn * NN + kc0 + shalf * 8;

    float D[2][8][4] = {};
    uint4 psh = *(const uint4*)sph;
    uint4 psl = *(const uint4*)spl;

    for (int it = 0; it < NIT2; it++) {
        *(uint4*)&Sh[sn][shalf*8] = psh;
        *(uint4*)&Sl[sn][shalf*8] = psl;
        __syncthreads();
        if (it + 1 < NIT2) {
            sph += 16; spl += 16;
            psh = *(const uint4*)sph;
            psl = *(const uint4*)spl;
        }
        unsigned a_h[2][4], a_l[2][4];
        #pragma unroll
        for (int mi = 0; mi < 2; mi++) {
            int row = warpM*32 + mi*16 + fr;
            a_h[mi][0] = *(const unsigned*)&Sh[row][kp];
            a_h[mi][1] = *(const unsigned*)&Sh[row+8][kp];
            a_h[mi][2] = *(const unsigned*)&Sh[row][kp+8];
            a_h[mi][3] = *(const unsigned*)&Sh[row+8][kp+8];
            a_l[mi][0] = *(const unsigned*)&Sl[row][kp];
            a_l[mi][1] = *(const unsigned*)&Sl[row+8][kp];
            a_l[mi][2] = *(const unsigned*)&Sl[row][kp+8];
            a_l[mi][3] = *(const unsigned*)&Sl[row+8][kp+8];
        }
        unsigned b_h[8][2], b_l[8][2];
        #pragma unroll
        for (int nj = 0; nj < 8; nj++) {
            int n = warpN*64 + nj*8 + fr;
            b_h[nj][0] = *(const unsigned*)&Sh[n][kp];
            b_h[nj][1] = *(const unsigned*)&Sh[n][kp+8];
            b_l[nj][0] = *(const unsigned*)&Sl[n][kp];
            b_l[nj][1] = *(const unsigned*)&Sl[n][kp+8];
        }
        #pragma unroll
        for (int mi = 0; mi < 2; mi++)
            #pragma unroll
            for (int nj = 0; nj < 8; nj++) {
                mma16816(D[mi][nj], a_h[mi], b_h[nj]);
                mma16816(D[mi][nj], a_h[mi], b_l[nj]);
                mma16816(D[mi][nj], a_l[mi], b_h[nj]);
            }
        __syncthreads();
    }
    #pragma unroll
    for (int mi = 0; mi < 2; mi++)
        #pragma unroll
        for (int nj = 0; nj < 8; nj++) {
            int m = warpM*32 + mi*16 + (lane >> 2);
            int n = warpN*64 + nj*8 + ((lane & 3) << 1);
            if (n < KCLU) {
                if (m < KCLU)     atomicAdd(&g_ssm[m*KCLU + n],     D[mi][nj][0]);
                if (m + 8 < KCLU) atomicAdd(&g_ssm[(m+8)*KCLU + n], D[mi][nj][2]);
            }
            if (n + 1 < KCLU) {
                if (m < KCLU)     atomicAdd(&g_ssm[m*KCLU + n + 1],     D[mi][nj][1]);
                if (m + 8 < KCLU) atomicAdd(&g_ssm[(m+8)*KCLU + n + 1], D[mi][nj][3]);
            }
        }
}

// ---------------- K6: build token + LN1(l=0) + QKV(l=0); block 0 writes losses ----
__global__ __launch_bounds__(256) void k_tok0(const float* __restrict__ cls,
                                              const float* __restrict__ ln_g,
                                              const float* __restrict__ ln_b,
                                              const float* __restrict__ w,
                                              const float* __restrict__ b,
                                              float* __restrict__ out)
{
    const int row = blockIdx.x;
    const int tid = threadIdx.x;
    __shared__ float hs[64];
    __shared__ float red[64];
    __shared__ float r1[256], r2[256];
    float v = 0.f;
    if (tid < 64) {
        v = (row == 0) ? cls[tid] : g_pool[(row-1)*DD + tid];
        g_t[row*DD + tid] = v;
        red[tid] = v;
    }
    __syncthreads();
    for (int s2 = 32; s2 > 0; s2 >>= 1) { if (tid < s2) red[tid] += red[tid+s2]; __syncthreads(); }
    float mean = red[0] * (1.0f/64);
    __syncthreads();
    if (tid < 64) { float d = v - mean; red[tid] = d*d; }
    __syncthreads();
    for (int s2 = 32; s2 > 0; s2 >>= 1) { if (tid < s2) red[tid] += red[tid+s2]; __syncthreads(); }
    float var = red[0] * (1.0f/64);
    __syncthreads();
    if (tid < 64)
        hs[tid] = (v - mean) * rsqrtf(var + 1e-6f) * ln_g[tid] + ln_b[tid];
    __syncthreads();
    if (tid < 192) {
        float a = b[tid];
        const float* wp = w + tid;
        #pragma unroll 8
        for (int d = 0; d < 64; d++) a += hs[d] * wp[d*192];
        g_qkvb[0][row*192 + tid] = a;
    }
    if (row == 0) {
        float sq = 0.f, tr = 0.f;
        for (int i = tid; i < KCLU*KCLU; i += 256) {
            float x = g_ssm[i];
            sq += x*x;
            if (i % (KCLU+1) == 0) tr += x;
        }
        r1[tid] = sq; r2[tid] = tr;
        __syncthreads();
        for (int s2 = 128; s2 > 0; s2 >>= 1) { if (tid < s2) { r1[tid]+=r1[tid+s2]; r2[tid]+=r2[tid+s2]; } __syncthreads(); }
        if (tid == 0) {
            float f = sqrtf(r1[0]);
            out[2] = -(g_num / g_den);
            out[3] = sqrtf(fmaxf(2.0f - r2[0] / (5.0f * f), 0.0f));
        }
    }
}

// ---------------- K7: attn + proj + LN2 + FC1 + GELU + FC2, then next LN1+QKV or head ----
__global__ __launch_bounds__(256) void k_fused(const float* __restrict__ proj_w,
                                               const float* __restrict__ proj_b,
                                               const float* __restrict__ ln2_g,
                                               const float* __restrict__ ln2_b,
                                               const float* __restrict__ fc1_w,
                                               const float* __restrict__ fc1_b,
                                               const float* __restrict__ fc2_w,
                                               const float* __restrict__ fc2_b,
                                               const float* __restrict__ ln1_g,
                                               const float* __restrict__ ln1_b,
                                               const float* __restrict__ qkv_w,
                                               const float* __restrict__ qkv_b,
                                               const float* __restrict__ norm_g,
                                               const float* __restrict__ norm_b,
                                               const float* __restrict__ head_w,
                                               const float* __restrict__ head_b,
                                               float* __restrict__ out,
                                               int l, int final_flag)
{
    const int row = blockIdx.x;
    const int tid = threadIdx.x;
    const int lane = tid & 31, wid = tid >> 5;
    const float* qin = g_qkvb[l & 1];
    float*       qout = g_qkvb[(l + 1) & 1];
    __shared__ float osm[64];
    __shared__ float hs[64];
    __shared__ float red[64];
    __shared__ float h1s[256];

    {
        const int h8 = wid * 8;
        float qv[8];
        #pragma unroll
        for (int d = 0; d < 8; d++) qv[d] = qin[row*192 + h8 + d];
        float sc[4];
        #pragma unroll
        for (int i = 0; i < 4; i++) {
            int j = lane + 32*i;
            float s = -3.0e38f;
            if (j < TOK) {
                const float* kp = qin + j*192 + 64 + h8;
                s = 0.f;
                #pragma unroll
                for (int d = 0; d < 8; d++) s += qv[d]*kp[d];
                s *= 0.35355339059327373f;
            }
            sc[i] = s;
        }
        float mx = fmaxf(fmaxf(sc[0],sc[1]), fmaxf(sc[2],sc[3]));
        #pragma unroll
        for (int off=16; off; off>>=1) mx = fmaxf(mx, __shfl_xor_sync(0xffffffffu, mx, off));
        float es[4]; float sum = 0.f;
        #pragma unroll
        for (int i = 0; i < 4; i++) {
            int j = lane + 32*i;
            es[i] = (j < TOK) ? expf(sc[i] - mx) : 0.f;
            sum += es[i];
        }
        #pragma unroll
        for (int off=16; off; off>>=1) sum += __shfl_xor_sync(0xffffffffu, sum, off);
        float inv = 1.0f / sum;
        float acc[8] = {};
        #pragma unroll
        for (int i = 0; i < 4; i++) {
            int j = lane + 32*i;
            if (j < TOK) {
                float p = es[i] * inv;
                const float* vp = qin + j*192 + 128 + h8;
                #pragma unroll
                for (int d = 0; d < 8; d++) acc[d] += p * vp[d];
            }
        }
        #pragma unroll
        for (int d = 0; d < 8; d++) {
            #pragma unroll
            for (int off=16; off; off>>=1) acc[d] += __shfl_xor_sync(0xffffffffu, acc[d], off);
        }
        if (lane == 0) {
            #pragma unroll
            for (int d = 0; d < 8; d++) osm[h8 + d] = acc[d];
        }
    }
    __syncthreads();

    float tnew = 0.f;
    if (tid < 64) {
        float a = proj_b[l*64 + tid];
        const float* wp = proj_w + (size_t)l*64*64 + tid;
        #pragma unroll 8
        for (int k = 0; k < 64; k++) a += osm[k] * wp[k*64];
        tnew = g_t[row*DD + tid] + a;
        red[tid] = tnew;
    }
    __syncthreads();
    for (int s2 = 32; s2 > 0; s2 >>= 1) { if (tid < s2) red[tid] += red[tid+s2]; __syncthreads(); }
    float mean = red[0] * (1.0f/64);
    __syncthreads();
    if (tid < 64) { float d = tnew - mean; red[tid] = d*d; }
    __syncthreads();
    for (int s2 = 32; s2 > 0; s2 >>= 1) { if (tid < s2) red[tid] += red[tid+s2]; __syncthreads(); }
    float var = red[0] * (1.0f/64);
    __syncthreads();
    if (tid < 64)
        hs[tid] = (tnew - mean) * rsqrtf(var + 1e-6f) * ln2_g[l*64 + tid] + ln2_b[l*64 + tid];
    __syncthreads();

    {
        float a = fc1_b[l*256 + tid];
        const float* wp = fc1_w + (size_t)l*64*256 + tid;
        #pragma unroll 8
        for (int d = 0; d < 64; d++) a += hs[d] * wp[d*256];
        h1s[tid] = 0.5f * a * (1.0f + erff(a * 0.7071067811865475f));
    }
    __syncthreads();

    float tfin = 0.f;
    if (tid < 64) {
        float a = fc2_b[l*64 + tid];
        const float* wp = fc2_w + (size_t)l*256*64 + tid;
        #pragma unroll 8
        for (int k = 0; k < 256; k++) a += h1s[k] * wp[k*64];
        tfin = tnew + a;
        red[tid] = tfin;
    }
    __syncthreads();
    for (int s2 = 32; s2 > 0; s2 >>= 1) { if (tid < s2) red[tid] += red[tid+s2]; __syncthreads(); }
    float mean2 = red[0] * (1.0f/64);
    __syncthreads();
    if (tid < 64) { float d = tfin - mean2; red[tid] = d*d; }
    __syncthreads();
    for (int s2 = 32; s2 > 0; s2 >>= 1) { if (tid < s2) red[tid] += red[tid+s2]; __syncthreads(); }
    float var2 = red[0] * (1.0f/64);
    __syncthreads();

    if (!final_flag) {
        if (tid < 64) {
            g_t[row*DD + tid] = tfin;
            hs[tid] = (tfin - mean2) * rsqrtf(var2 + 1e-6f) * ln1_g[(l+1)*64 + tid] + ln1_b[(l+1)*64 + tid];
        }
        __syncthreads();
        if (tid < 192) {
            float a = qkv_b[(l+1)*192 + tid];
            const float* wp = qkv_w + (size_t)(l+1)*64*192 + tid;
            #pragma unroll 8
            for (int d = 0; d < 64; d++) a += hs[d] * wp[d*192];
            qout[row*192 + tid] = a;
        }
    } else {
        float h = 0.f;
        if (tid < 64)
            h = (tfin - mean2) * rsqrtf(var2 + 1e-6f) * norm_g[tid] + norm_b[tid];
        #pragma unroll
        for (int c = 0; c < 2; c++) {
            if (tid < 64) red[tid] = h * head_w[tid*2 + c];
            __syncthreads();
            for (int s2 = 32; s2 > 0; s2 >>= 1) { if (tid < s2) red[tid] += red[tid+s2]; __syncthreads(); }
            if (tid == 0) out[c] = red[0] + head_b[c];
            __syncthreads();
        }
    }
}

// ---------------- launcher ----------------
extern "C" void kernel_launch(void* const* d_in, const int* in_sizes, int n_in,
                              void* d_out, int out_size)
{
    const float* node   = (const float*)d_in[0];
    const float* adj    = (const float*)d_in[1];
    const float* conv_w = (const float*)d_in[2];
    const float* conv_b = (const float*)d_in[3];
    const float* bn_g   = (const float*)d_in[4];
    const float* bn_b   = (const float*)d_in[5];
    const float* pool_w = (const float*)d_in[6];
    const float* pool_b = (const float*)d_in[7];
    const float* cls    = (const float*)d_in[8];
    const float* ln1_g  = (const float*)d_in[9];
    const float* ln1_b  = (const float*)d_in[10];
    const float* qkv_w  = (const float*)d_in[11];
    const float* qkv_b  = (const float*)d_in[12];
    const float* proj_w = (const float*)d_in[13];
    const float* proj_b = (const float*)d_in[14];
    const float* ln2_g  = (const float*)d_in[15];
    const float* ln2_b  = (const float*)d_in[16];
    const float* fc1_w  = (const float*)d_in[17];
    const float* fc1_b  = (const float*)d_in[18];
    const float* fc2_w  = (const float*)d_in[19];
    const float* fc2_b  = (const float*)d_in[20];
    const float* norm_g = (const float*)d_in[21];
    const float* norm_b = (const float*)d_in[22];
    const float* head_w = (const float*)d_in[23];
    const float* head_b = (const float*)d_in[24];
    float* out = (float*)d_out;

    k_gemm_xc<<<NN/64, 256>>>(node, conv_w);
    k_init<<<(NN*DD)/256, 256>>>(conv_b);
    k_xcT<<<NN/64, 256>>>();
    k_pass1<<<dim3(NN/64, KSPLIT), 256>>>(adj);
    k_bnstats<<<NN/64, 256>>>();
    k_rowops<<<NN/8, 256>>>(bn_g, bn_b, pool_w, pool_b);
    k_pass2<<<dim3(NN/64, KSPLIT), 256>>>(adj);
    k_poolT<<<PSPLIT, 256>>>();
    k_ssT<<<PSPLIT, 256>>>();
    k_tok0<<<TOK, 256>>>(cls, ln1_g, ln1_b, qkv_w, qkv_b, out);
    k_fused<<<TOK, 256>>>(proj_w, proj_b, ln2_g, ln2_b, fc1_w, fc1_b, fc2_w, fc2_b,
                          ln1_g, ln1_b, qkv_w, qkv_b, norm_g, norm_b, head_w, head_b,
                          out, 0, 0);
    k_fused<<<TOK, 256>>>(proj_w, proj_b, ln2_g, ln2_b, fc1_w, fc1_b, fc2_w, fc2_b,
                          ln1_g, ln1_b, qkv_w, qkv_b, norm_g, norm_b, head_w, head_b,
                          out, 1, 0);
    k_fused<<<1, 256>>>(proj_w, proj_b, ln2_g, ln2_b, fc1_w, fc1_b, fc2_w, fc2_b,
                        ln1_g, ln1_b, qkv_w, qkv_b, norm_g, norm_b, head_w, head_b,
                        out, 2, 1);
}